// round 13
// baseline (speedup 1.0000x reference)
#include <cuda_runtime.h>
#include <cuda_fp16.h>
#include <cstdint>
#include <math.h>

#define NB    16
#define NL    1536
#define ND    512
#define NDFF  2048
#define NTOPK 7
#define NBLD  (NB*NL*ND)
#define NH    (NB*NL*NDFF)
#define DDW   262144            // 512*512
#define MTOT  (NB*NL)           // 24576

// ------------------------------- scratch ------------------------------------
__device__ float g_xs[NBLD];
__device__ float g_xs2[NBLD];
__device__ float g_tmp[NBLD];
__device__ float g_v32[NBLD];
__device__ float g_mean[NB*NL];
__device__ int   g_idx[NTOPK];
__device__ float g_wt[NB*NTOPK];
__device__ float g_b1024[3*1024];   // merged-GEMM bias per stage: [0]*512 ++ bfull

// fp16 arenas
__device__ __half g_wf[20*DDW];   // wc1(4) attn(4) wc2(4) conv1(4) conv2(4)
__device__ __half g_weh[6*DDW];   // embed weights (wc1_proj 0-2, wc2_proj 3-5)
__device__ __half g_wmv[6*DDW];   // per stage: [M ; Wvo]
__device__ __half g_wtt[3*DDW];   // transpose scratch (WqT, WkT, WvT)
__device__ __half fXW[NBLD];
__device__ __half fXSI[NBLD];
__device__ __half fK[NBLD], fV[NBLD];
__device__ __half fXSa[NBLD], fXS2[NBLD];
__device__ __half fXW1[NBLD];
__device__ __half fXSB[NBLD];
__device__ __half fH[NH];

// ------------------------------- helpers -------------------------------------
__device__ __forceinline__ uint32_t smem_u32(const void* p){
    uint32_t a;
    asm("{ .reg .u64 t; cvta.to.shared.u64 t, %1; cvt.u32.u64 %0, t; }":"=r"(a):"l"(p));
    return a;
}
__device__ __forceinline__ void cp16(uint32_t s, const void* g){
    asm volatile("cp.async.cg.shared.global [%0], [%1], 16;"::"r"(s),"l"(g));
}
__device__ __forceinline__ void cp_commit(){
    asm volatile("cp.async.commit_group;":::"memory");
}
__device__ __forceinline__ void ldm4(uint32_t* r, uint32_t a){
    asm volatile("ldmatrix.sync.aligned.m8n8.x4.shared.b16 {%0,%1,%2,%3}, [%4];"
        : "=r"(r[0]),"=r"(r[1]),"=r"(r[2]),"=r"(r[3]) : "r"(a));
}
__device__ __forceinline__ void mma16816f(float* c, const uint32_t* a, uint32_t b0, uint32_t b1){
    asm volatile("mma.sync.aligned.m16n8k16.row.col.f32.f16.f16.f32 "
        "{%0,%1,%2,%3},{%4,%5,%6,%7},{%8,%9},{%0,%1,%2,%3};"
        : "+f"(c[0]),"+f"(c[1]),"+f"(c[2]),"+f"(c[3])
        : "r"(a[0]),"r"(a[1]),"r"(a[2]),"r"(a[3]), "r"(b0),"r"(b1));
}
#define SWZ(o) ((o) ^ (((o) >> 3) & 0x70))
#define SSTG 32768u

#define WARP_SETUP() \
    int wm = wid >> 2, wn = wid & 3; \
    int rowA = (wm << 6) + (lane & 15); \
    int rowB = (wn << 5) + (lane & 15); \
    uint32_t sA = rowA & 7, sB = rowB & 7, cq = lane >> 4; \
    uint32_t aB[4], bB[2]; \
    _Pragma("unroll") for (int mi = 0; mi < 4; mi++) aB[mi] = (uint32_t)(rowA + (mi<<4)) * 128; \
    _Pragma("unroll") for (int nj = 0; nj < 2; nj++) bB[nj] = (uint32_t)(rowB + (nj<<4)) * 128; \
    float acc[4][4][4]; \
    _Pragma("unroll") for (int mi = 0; mi < 4; mi++) \
        _Pragma("unroll") for (int ni = 0; ni < 4; ni++) \
            _Pragma("unroll") for (int e2 = 0; e2 < 4; e2++) acc[mi][ni][e2] = 0.f;

#define MMA_CHUNK_1T(stgbase) do{ \
    _Pragma("unroll") \
    for (int ks = 0; ks < 4; ks++){ \
        uint32_t ah[4][4], bh[2][4]; \
        uint32_t ca = ((((ks<<1)|cq) ^ sA) << 4); \
        uint32_t cb = ((((ks<<1)|cq) ^ sB) << 4); \
        _Pragma("unroll") \
        for (int mi = 0; mi < 4; mi++) ldm4(ah[mi], (stgbase) + aB[mi] + ca); \
        _Pragma("unroll") \
        for (int nj = 0; nj < 2; nj++) ldm4(bh[nj], (stgbase) + bB[nj] + cb + 16384); \
        _Pragma("unroll") \
        for (int mi = 0; mi < 4; mi++) \
            _Pragma("unroll") \
            for (int ni = 0; ni < 4; ni++){ \
                uint32_t g = ni >> 1, s = ni & 1; \
                mma16816f(acc[mi][ni], ah[mi], bh[g][s], bh[g][s+2]); \
            } \
    } \
}while(0)

// ------------------------------- single-term fp16 GEMM -----------------------
// C[m,n] = act( sum_k A[m,k]*W[n,k] + bias[n] + R[m,n] )
// If C16b != null: merged mode; column block j = n>>9 routes to
// {C16, C16b, C16c}[j] with row stride 512.
__global__ void __launch_bounds__(256,2)
gemm_s(const __half* __restrict__ A, const __half* __restrict__ W,
       const float* __restrict__ bias, const float* __restrict__ R,
       float* Cf, __half* C16, __half* C16b, __half* C16c,
       int N, int K, int relu)
{
    extern __shared__ char smem[];
    uint32_t sb = smem_u32(smem);
    int tid = threadIdx.x, wid = tid >> 5, lane = tid & 31;
    int m0 = blockIdx.y << 7, n0 = blockIdx.x << 7;

    size_t aoff[4], boff[4];
    uint32_t soff[4];
    #pragma unroll
    for (int i = 0; i < 4; i++){
        int idx = tid + (i << 8);
        int r = idx >> 3, u = idx & 7;
        aoff[i] = (size_t)(m0 + r) * K + u * 8;
        boff[i] = (size_t)(n0 + r) * K + u * 8;
        soff[i] = SWZ((uint32_t)(r * 128 + u * 16));
    }
    WARP_SETUP();

    int nch = K >> 6;
    {
        #pragma unroll
        for (int i = 0; i < 4; i++){
            cp16(sb + soff[i],         A + aoff[i]);
            cp16(sb + 16384 + soff[i], W + boff[i]);
        }
        cp_commit();
    }
    for (int c = 0; c < nch; c++){
        if (c + 1 < nch){
            uint32_t sp_ = sb + ((c+1)&1)*SSTG;
            size_t k0 = (size_t)(c+1) << 6;
            #pragma unroll
            for (int i = 0; i < 4; i++){
                cp16(sp_ + soff[i],         A + aoff[i] + k0);
                cp16(sp_ + 16384 + soff[i], W + boff[i] + k0);
            }
            cp_commit();
            asm volatile("cp.async.wait_group 1;":::"memory");
        } else {
            asm volatile("cp.async.wait_group 0;":::"memory");
        }
        __syncthreads();
        MMA_CHUNK_1T(sb + (c & 1)*SSTG);
        __syncthreads();
    }

    int gm = m0 + (wm << 6) + (lane >> 2);
    int gn = n0 + (wn << 5) + ((lane & 3) << 1);
    #pragma unroll
    for (int mi = 0; mi < 4; mi++)
        #pragma unroll
        for (int ni = 0; ni < 4; ni++)
            #pragma unroll
            for (int hh = 0; hh < 2; hh++){
                int rr = gm + (mi << 4) + hh * 8;
                int cc = gn + (ni << 3);
                float v0 = acc[mi][ni][hh*2+0];
                float v1 = acc[mi][ni][hh*2+1];
                if (bias){ v0 += bias[cc]; v1 += bias[cc+1]; }
                if (C16b){
                    int j = cc >> 9, c2 = cc & 511;
                    __half* dst = (j == 0) ? C16 : ((j == 1) ? C16b : C16c);
                    *reinterpret_cast<__half2*>(dst + (size_t)rr * 512 + c2) =
                        __floats2half2_rn(v0, v1);
                } else {
                    size_t o = (size_t)rr * N + cc;
                    if (R){ float2 r2 = *reinterpret_cast<const float2*>(R + o); v0 += r2.x; v1 += r2.y; }
                    if (relu){ v0 = fmaxf(v0, 0.f); v1 = fmaxf(v1, 0.f); }
                    if (Cf)  *reinterpret_cast<float2*>(Cf + o)  = make_float2(v0, v1);
                    if (C16) *reinterpret_cast<__half2*>(C16 + o) = __floats2half2_rn(v0, v1);
                }
            }
}

// --------------------------- fused token-embed (single-term) -----------------
__global__ void __launch_bounds__(256,2)
embed_f16(const __half* __restrict__ A, const __half* __restrict__ B,
          float* Cf, __half* Ch)
{
    extern __shared__ char smem[];
    uint32_t sb = smem_u32(smem);
    int tid = threadIdx.x, wid = tid >> 5, lane = tid & 31;
    int m0 = blockIdx.y << 7, n0 = blockIdx.x << 7;

    size_t aoff0[4], boff[4];
    int dm1[4], dp1[4];
    uint32_t soff[4];
    #pragma unroll
    for (int i = 0; i < 4; i++){
        int idx = tid + (i << 8);
        int r = idx >> 3, u = idx & 7;
        int am = m0 + r;
        int b = am / NL;
        int t = am - b * NL;
        aoff0[i] = (size_t)am * ND + u * 8;
        dm1[i] = ((t == 0    ? NL - 1 : t - 1) - t) * ND;
        dp1[i] = ((t == NL-1 ? 0      : t + 1) - t) * ND;
        boff[i] = (size_t)(n0 + r) * ND + u * 8;
        soff[i] = SWZ((uint32_t)(r * 128 + u * 16));
    }
    WARP_SETUP();

    #define ELOAD(stage, c_) do{ \
        int tap_ = (c_) >> 3; \
        int kb_ = ((c_) & 7) << 6; \
        size_t bo_ = (size_t)tap_ * DDW + kb_; \
        uint32_t sp_ = sb + (stage)*SSTG; \
        _Pragma("unroll") \
        for (int i_ = 0; i_ < 4; i_++){ \
            long ao_ = (long)aoff0[i_] + (tap_ == 0 ? dm1[i_] : (tap_ == 2 ? dp1[i_] : 0)) + kb_; \
            cp16(sp_ + soff[i_],          A + ao_); \
            cp16(sp_ + 16384 + soff[i_],  B + boff[i_] + bo_); \
        } \
        cp_commit(); \
    }while(0)

    ELOAD(0, 0);
    for (int c = 0; c < 24; c++){
        if (c + 1 < 24){
            ELOAD((c+1)&1, c+1);
            asm volatile("cp.async.wait_group 1;":::"memory");
        } else {
            asm volatile("cp.async.wait_group 0;":::"memory");
        }
        __syncthreads();
        MMA_CHUNK_1T(sb + (c & 1)*SSTG);
        __syncthreads();
    }
    #undef ELOAD

    int gm = m0 + (wm << 6) + (lane >> 2);
    int gn = n0 + (wn << 5) + ((lane & 3) << 1);
    #pragma unroll
    for (int mi = 0; mi < 4; mi++)
        #pragma unroll
        for (int ni = 0; ni < 4; ni++)
            #pragma unroll
            for (int hh = 0; hh < 2; hh++){
                int rr = gm + (mi << 4) + hh * 8;
                int cc = gn + (ni << 3);
                float v0 = acc[mi][ni][hh*2+0];
                float v1 = acc[mi][ni][hh*2+1];
                size_t o = (size_t)rr * ND + cc;
                if (Cf) *reinterpret_cast<float2*>(Cf + o) = make_float2(v0, v1);
                if (Ch) *reinterpret_cast<__half2*>(Ch + o) = __floats2half2_rn(v0, v1);
            }
}

// --------------------------- correlation (fp16, 1-term) ----------------------
// g_mean[b,tau] += (1/512) * sum over (t,s): (t-s)%L==tau of <Xq_t, Kt_s>
__global__ void __launch_bounds__(256,2)
corr_f16(const __half* __restrict__ Qf, const __half* __restrict__ Kf)
{
    extern __shared__ char smem[];
    uint32_t sb = smem_u32(smem);
    int tid = threadIdx.x, wid = tid >> 5, lane = tid & 31;
    int bb = blockIdx.z;
    size_t base = (size_t)bb * NL * ND;
    int m0 = blockIdx.y << 7, n0 = blockIdx.x << 7;

    size_t aoff[4], boff[4];
    uint32_t soff[4];
    #pragma unroll
    for (int i = 0; i < 4; i++){
        int idx = tid + (i << 8);
        int r = idx >> 3, u = idx & 7;
        aoff[i] = base + (size_t)(m0 + r) * ND + u * 8;
        boff[i] = base + (size_t)(n0 + r) * ND + u * 8;
        soff[i] = SWZ((uint32_t)(r * 128 + u * 16));
    }
    WARP_SETUP();

    {
        #pragma unroll
        for (int i = 0; i < 4; i++){
            cp16(sb + soff[i],          Qf + aoff[i]);
            cp16(sb + 16384 + soff[i],  Kf + boff[i]);
        }
        cp_commit();
    }
    for (int c = 0; c < 8; c++){
        if (c + 1 < 8){
            uint32_t sp_ = sb + ((c+1)&1)*SSTG;
            size_t k0 = (size_t)(c+1) << 6;
            #pragma unroll
            for (int i = 0; i < 4; i++){
                cp16(sp_ + soff[i],          Qf + aoff[i] + k0);
                cp16(sp_ + 16384 + soff[i],  Kf + boff[i] + k0);
            }
            cp_commit();
            asm volatile("cp.async.wait_group 1;":::"memory");
        } else {
            asm volatile("cp.async.wait_group 0;":::"memory");
        }
        __syncthreads();
        MMA_CHUNK_1T(sb + (c & 1)*SSTG);
        __syncthreads();
    }

    float* bins = reinterpret_cast<float*>(smem);
    if (tid < 255) bins[tid] = 0.f;
    __syncthreads();

    int lm = (wm << 6) + (lane >> 2);
    int ln = (wn << 5) + ((lane & 3) << 1);
    #pragma unroll
    for (int mi = 0; mi < 4; mi++)
        #pragma unroll
        for (int ni = 0; ni < 4; ni++)
            #pragma unroll
            for (int hh = 0; hh < 2; hh++){
                int rr = lm + (mi << 4) + hh * 8;
                int cc = ln + (ni << 3);
                atomicAdd(&bins[rr - cc + 127],     acc[mi][ni][hh*2+0]);
                atomicAdd(&bins[rr - cc - 1 + 127], acc[mi][ni][hh*2+1]);
            }
    __syncthreads();
    if (tid < 255){
        int tau = m0 - n0 + tid - 127;
        tau %= NL; if (tau < 0) tau += NL;
        atomicAdd(&g_mean[bb * NL + tau], bins[tid] * (1.f / 512.f));
    }
}

// ------------------------------ small kernels --------------------------------
__global__ void cvt_f16s(const float* __restrict__ x, __half* __restrict__ o, int n4)
{
    int i = blockIdx.x * blockDim.x + threadIdx.x;
    if (i >= n4) return;
    float4 v = reinterpret_cast<const float4*>(x)[i];
    __half2* op = reinterpret_cast<__half2*>(o);
    op[2*i]   = __floats2half2_rn(v.x, v.y);
    op[2*i+1] = __floats2half2_rn(v.z, v.w);
}

__global__ void cvt_proj_f16(const float* __restrict__ src, __half* __restrict__ h)
{
    int e = blockIdx.x * blockDim.x + threadIdx.x;
    if (e >= DDW) return;
    int n = e >> 9, k = e & 511;
    h[e] = __float2half_rn(src[n * 1536 + k * 3]);
}

// 512x512 fp32 -> fp16 transpose
__global__ void transpose_w(const float* __restrict__ src, __half* __restrict__ dst)
{
    __shared__ float tile[32][33];
    int bx = blockIdx.x << 5, by = blockIdx.y << 5;
    int tx = threadIdx.x, ty = threadIdx.y;   // (32, 8)
    #pragma unroll
    for (int j = 0; j < 32; j += 8)
        tile[ty + j][tx] = src[(size_t)(by + ty + j) * 512 + bx + tx];
    __syncthreads();
    #pragma unroll
    for (int j = 0; j < 32; j += 8)
        dst[(size_t)(bx + ty + j) * 512 + by + tx] = __float2half_rn(tile[tx][ty + j]);
}

// merged bias: [0..511] = 0 (k~), [512..1023] = Wo·bv + bo
__global__ void mkbias(const float* __restrict__ Wo, const float* __restrict__ bv,
                       const float* __restrict__ bo, float* __restrict__ b1024)
{
    int n = threadIdx.x;   // 512
    b1024[n] = 0.f;
    float s = bo[n];
    for (int e = 0; e < 512; e++) s += Wo[(size_t)n * 512 + e] * bv[e];
    b1024[512 + n] = s;
}

__global__ void topk_kernel()
{
    __shared__ float gv[NL];
    __shared__ float rv[512];
    __shared__ int   ri[512];
    __shared__ int   sidx[NTOPK];
    int tid = threadIdx.x;
    for (int t = tid; t < NL; t += 512) {
        float s = 0.f;
        for (int b = 0; b < NB; b++) s += g_mean[b * NL + t];
        gv[t] = s;
    }
    __syncthreads();
    for (int it = 0; it < NTOPK; it++) {
        float bv = -INFINITY; int bi = 0x7fffffff;
        for (int t = tid; t < NL; t += 512) {
            float v = gv[t];
            if (v > bv || (v == bv && t < bi)) { bv = v; bi = t; }
        }
        rv[tid] = bv; ri[tid] = bi;
        __syncthreads();
        for (int s = 256; s > 0; s >>= 1) {
            if (tid < s) {
                if (rv[tid+s] > rv[tid] || (rv[tid+s] == rv[tid] && ri[tid+s] < ri[tid])) {
                    rv[tid] = rv[tid+s]; ri[tid] = ri[tid+s];
                }
            }
            __syncthreads();
        }
        if (tid == 0) { sidx[it] = ri[0]; gv[ri[0]] = -INFINITY; }
        __syncthreads();
    }
    if (tid < NTOPK) g_idx[tid] = sidx[tid];
    if (tid < NB) {
        float vals[NTOPK];
        float mx = -INFINITY;
        for (int i = 0; i < NTOPK; i++) {
            vals[i] = g_mean[tid * NL + sidx[i]];
            mx = fmaxf(mx, vals[i]);
        }
        float s = 0.f;
        for (int i = 0; i < NTOPK; i++) { vals[i] = expf(vals[i] - mx); s += vals[i]; }
        float inv = 1.f / s;
        for (int i = 0; i < NTOPK; i++) g_wt[tid * NTOPK + i] = vals[i] * inv;
    }
}

// time-delay aggregation + residual: Of = R + sum_i w_i * V'(t+delta_i)
__global__ void roll_kernel(const __half* __restrict__ V16, const float* __restrict__ R,
                            float* __restrict__ Of, __half* __restrict__ O16)
{
    int e = blockIdx.x * blockDim.x + threadIdx.x;
    if (e >= NBLD/2) return;
    int dh = e & 255;
    int row = e >> 8;
    int b = row / NL;
    int t = row - b * NL;
    float2 r2 = *reinterpret_cast<const float2*>(R + (size_t)row * ND + dh*2);
    float sx = r2.x, sy = r2.y;
    #pragma unroll
    for (int i = 0; i < NTOPK; i++) {
        int tt = t + g_idx[i];
        if (tt >= NL) tt -= NL;
        __half2 v = *reinterpret_cast<const __half2*>(V16 + ((size_t)(b*NL + tt))*ND + dh*2);
        float2 vf = __half22float2(v);
        float w = g_wt[b * NTOPK + i];
        sx += w * vf.x; sy += w * vf.y;
    }
    *reinterpret_cast<float2*>(Of + (size_t)row * ND + dh*2) = make_float2(sx, sy);
    if (O16)
        *reinterpret_cast<__half2*>(O16 + (size_t)row * ND + dh*2) = __floats2half2_rn(sx, sy);
}

__global__ void decomp_kernel(const float* __restrict__ X, float* __restrict__ Of,
                              __half* O16)
{
    int i = blockIdx.x * blockDim.x + threadIdx.x;
    if (i >= NBLD/8) return;
    int d = i & 511;
    int c = i >> 9;
    int b = c / (NL/8);
    int tb = (c - b * (NL/8)) * 8;
    const float* Xb = X + (size_t)b * NL * ND + d;

    float acc = 0.f;
    #pragma unroll
    for (int u = -12; u <= 12; u++){
        int t = tb + u;
        t = t < 0 ? 0 : (t >= NL ? NL - 1 : t);
        acc += Xb[(size_t)t * ND];
    }
    #pragma unroll
    for (int j = 0; j < 8; j++){
        int t = tb + j;
        float x = Xb[(size_t)t * ND];
        float v = x - acc * (1.f / 25.f);
        size_t e = ((size_t)b * NL + t) * ND + d;
        if (Of)  Of[e]  = v;
        if (O16) O16[e] = __float2half_rn(v);
        int ta = t + 13; ta = ta >= NL ? NL - 1 : ta;
        int ts = t - 12; ts = ts < 0 ? 0 : ts;
        acc += Xb[(size_t)ta * ND] - Xb[(size_t)ts * ND];
    }
}

// ------------------------------- host side -----------------------------------
#define GETSYM(var, sym) do{ cudaGetSymbolAddress((void**)&var, sym); }while(0)

extern "C" void kernel_launch(void* const* d_in, const int* in_sizes, int n_in,
                              void* d_out, int out_size)
{
    const float* x_s      = (const float*)d_in[0];
    const float* x_w      = (const float*)d_in[1];
    const float* wc1_W    = (const float*)d_in[2];
    const float* wc1_b    = (const float*)d_in[3];
    const float* wc2_W    = (const float*)d_in[4];
    const float* wc2_b    = (const float*)d_in[5];
    const float* attn_W   = (const float*)d_in[6];
    const float* attn_b   = (const float*)d_in[7];
    const float* wc1_proj = (const float*)d_in[8];
    const float* wc2_proj = (const float*)d_in[9];
    const float* conv1_W  = (const float*)d_in[10];
    const float* conv2_W  = (const float*)d_in[11];
    float* out  = (float*)d_out;
    float* out2 = out + NBLD;

    float *pxs, *pxs2, *ptmp, *pv32, *pmean, *pb1024;
    GETSYM(pxs, g_xs); GETSYM(pxs2, g_xs2); GETSYM(ptmp, g_tmp);
    GETSYM(pv32, g_v32); GETSYM(pmean, g_mean); GETSYM(pb1024, g_b1024);
    __half *wf, *pweh, *pwmv, *pwtt;
    GETSYM(wf, g_wf); GETSYM(pweh, g_weh); GETSYM(pwmv, g_wmv); GETSYM(pwtt, g_wtt);
    __half *pfXW,*pfXSI,*pfK,*pfV,*pfXSa,*pfXS2,*pfXW1,*pfXSB,*pfH;
    GETSYM(pfXW, fXW);   GETSYM(pfXSI, fXSI);
    GETSYM(pfK, fK);     GETSYM(pfV, fV);
    GETSYM(pfXSa, fXSa); GETSYM(pfXS2, fXS2);
    GETSYM(pfXW1, fXW1); GETSYM(pfXSB, fXSB); GETSYM(pfH, fH);

    cudaFuncSetAttribute(gemm_s,    cudaFuncAttributeMaxDynamicSharedMemorySize, 2*SSTG);
    cudaFuncSetAttribute(embed_f16, cudaFuncAttributeMaxDynamicSharedMemorySize, 2*SSTG);
    cudaFuncSetAttribute(corr_f16,  cudaFuncAttributeMaxDynamicSharedMemorySize, 2*SSTG);

    const int nRB = (NBLD/2 + 255) / 256;
    const int nDB = (NBLD/8 + 255) / 256;
    dim3 corrG(12, 12, NB);
    dim3 embG(4, 192);
    dim3 trG(16, 16), trB(32, 8);
    dim3 smG(4, 4);

    // plain GEMM over all tokens
    auto G = [&](const __half* A, int woff, const float* bias, const float* R,
                 float* Cf, __half* C16, int N, int K, int relu){
        dim3 g(N >> 7, MTOT >> 7);
        gemm_s<<<g, 256, 2*SSTG>>>(A, wf + (size_t)woff * DDW, bias, R,
                                   Cf, C16, nullptr, nullptr, N, K, relu);
    };
    // merged [k~ | v'] GEMM: N=1024, routed outputs
    auto Gm = [&](const __half* A, int stage){
        dim3 g(8, MTOT >> 7);
        gemm_s<<<g, 256, 2*SSTG>>>(A, pwmv + (size_t)stage * 2 * DDW,
                                   pb1024 + stage * 1024, nullptr,
                                   nullptr, pfK, pfV, pfV, 1024, ND, 0);
    };

    // ---- weight conversions -------------------------------------------------
    cvt_f16s<<<1024,256>>>(wc1_W,  wf +  0*(size_t)DDW, DDW);
    cvt_f16s<<<1024,256>>>(attn_W, wf +  4*(size_t)DDW, DDW);
    cvt_f16s<<<1024,256>>>(wc2_W,  wf +  8*(size_t)DDW, DDW);
    cvt_f16s<<<1024,256>>>(conv1_W,wf + 12*(size_t)DDW, DDW);
    cvt_f16s<<<1024,256>>>(conv2_W,wf + 16*(size_t)DDW, DDW);
    for (int j = 0; j < 3; j++){
        cvt_proj_f16<<<(DDW+255)/256,256>>>(wc1_proj + j, pweh + (size_t)j*DDW);
        cvt_proj_f16<<<(DDW+255)/256,256>>>(wc2_proj + j, pweh + (size_t)(3+j)*DDW);
    }
    cvt_f16s<<<(NBLD/4+255)/256,256>>>(x_w, pfXW,  NBLD/4);
    cvt_f16s<<<(NBLD/4+255)/256,256>>>(x_s, pfXSI, NBLD/4);

    // ---- folded weight products: M = Wq^T·Wk, Wvo = Wo·Wv, bias -------------
    {
        const float* Wsrc[3] = {wc1_W, attn_W, wc2_W};
        const float* bsrc[3] = {wc1_b, attn_b, wc2_b};
        const int    woIdx[3] = {3, 7, 11};   // Wo fp16 position in wf
        for (int s = 0; s < 3; s++){
            transpose_w<<<trG, trB>>>(Wsrc[s] + 0*DDW, pwtt + 0*(size_t)DDW);  // WqT
            transpose_w<<<trG, trB>>>(Wsrc[s] + 1*DDW, pwtt + 1*(size_t)DDW);  // WkT
            transpose_w<<<trG, trB>>>(Wsrc[s] + 2*DDW, pwtt + 2*(size_t)DDW);  // WvT
            // M[a,b] = sum_e WqT[a,e]*WkT[b,e] = (Wq^T Wk)[a,b]
            gemm_s<<<smG, 256, 2*SSTG>>>(pwtt, pwtt + DDW, nullptr, nullptr,
                nullptr, pwmv + (size_t)s*2*DDW, nullptr, nullptr, 512, 512, 0);
            // Wvo[a,b] = sum_e Wo[a,e]*WvT[b,e] = (Wo·Wv)[a,b]
            gemm_s<<<smG, 256, 2*SSTG>>>(wf + (size_t)woIdx[s]*DDW, pwtt + 2*DDW,
                nullptr, nullptr,
                nullptr, pwmv + (size_t)s*2*DDW + DDW, nullptr, nullptr, 512, 512, 0);
            mkbias<<<1, 512>>>(Wsrc[s] + 3*DDW, bsrc[s] + 2*ND, bsrc[s] + 3*ND,
                               pb1024 + s * 1024);
        }
    }

    // ---- stage A: x_s += attn(q=x_w, k=v=x_s, wc1) --------------------------
    Gm(pfXSI, 0);
    cudaMemsetAsync(pmean, 0, NB*NL*sizeof(float), 0);
    corr_f16<<<corrG, 256, 2*SSTG>>>(pfXW, pfK);
    topk_kernel<<<1, 512>>>();
    roll_kernel<<<nRB, 256>>>(pfV, x_s, pxs, pfXSa);

    // ---- stage B: xw1 = token_embed(x_w, wc1_proj) --------------------------
    embed_f16<<<embG, 256, 2*SSTG>>>(pfXW, pweh, nullptr, pfXW1);

    // ---- stage C: xs += attn(xs, xs, xs, attn_W) ----------------------------
    Gm(pfXSa, 1);
    cudaMemsetAsync(pmean, 0, NB*NL*sizeof(float), 0);
    corr_f16<<<corrG, 256, 2*SSTG>>>(pfXSa, pfK);
    topk_kernel<<<1, 512>>>();
    roll_kernel<<<nRB, 256>>>(pfV, pxs, pxs, nullptr);

    // ---- stage D: xs2 = series_decomp(xs) -----------------------------------
    decomp_kernel<<<nDB, 256>>>(pxs, pxs2, pfXS2);

    // ---- stage E: xs2' = xs2 + attn(q=xw1, k=v=xs2, wc2) --------------------
    Gm(pfXS2, 2);
    cudaMemsetAsync(pmean, 0, NB*NL*sizeof(float), 0);
    corr_f16<<<corrG, 256, 2*SSTG>>>(pfXW1, pfK);
    topk_kernel<<<1, 512>>>();
    roll_kernel<<<nRB, 256>>>(pfV, pxs2, ptmp, pfXSB);

    // ---- stage F: x_w_new = token_embed(xw1, wc2_proj) -> out2 --------------
    embed_f16<<<embG, 256, 2*SSTG>>>(pfXW1, pweh + 3*(size_t)DDW, out2, nullptr);

    // ---- stage G: FFN + final series_decomp -> out --------------------------
    G(pfXSB, 12, nullptr, nullptr, nullptr, pfH, NDFF, ND,   1);
    G(pfH,   16, nullptr, ptmp,    pv32,    nullptr, ND, NDFF, 0);
    decomp_kernel<<<nDB, 256>>>(pv32, out, nullptr);
}

// round 14
// speedup vs baseline: 1.2655x; 1.2655x over previous
#include <cuda_runtime.h>
#include <cuda_fp16.h>
#include <cstdint>
#include <math.h>

#define NB    16
#define NL    1536
#define ND    512
#define NDFF  2048
#define NTOPK 7
#define NBLD  (NB*NL*ND)
#define NH    (NB*NL*NDFF)
#define DDW   262144            // 512*512
#define MTOT  (NB*NL)           // 24576

// ------------------------------- scratch ------------------------------------
__device__ float g_xs[NBLD];
__device__ float g_xs2[NBLD];
__device__ float g_tmp[NBLD];
__device__ float g_v32[NBLD];
__device__ float g_mean[NB*NL];
__device__ int   g_idx[NTOPK];
__device__ float g_wt[NB*NTOPK];
__device__ float g_b1024[3*1024];   // merged-GEMM bias per stage: [0]*512 ++ bfull

// fp16 arenas
__device__ __half g_wf[20*DDW];   // wc1(4) attn(4) wc2(4) conv1(4) conv2(4)
__device__ __half g_weh[6*DDW];   // embed weights (wc1_proj 0-2, wc2_proj 3-5)
__device__ __half g_wmv[6*DDW];   // per stage: [M ; Wvo]
__device__ __half g_wtt[9*DDW];   // transposed Wq/Wk/Wv per stage
__device__ __half fXW[NBLD];
__device__ __half fXSI[NBLD];
__device__ __half fK[NBLD], fV[NBLD];
__device__ __half fXSa[NBLD], fXS2[NBLD];
__device__ __half fXW1[NBLD];
__device__ __half fXSB[NBLD];
__device__ __half fH[NH];

// ------------------------------- helpers -------------------------------------
__device__ __forceinline__ uint32_t smem_u32(const void* p){
    uint32_t a;
    asm("{ .reg .u64 t; cvta.to.shared.u64 t, %1; cvt.u32.u64 %0, t; }":"=r"(a):"l"(p));
    return a;
}
__device__ __forceinline__ void cp16(uint32_t s, const void* g){
    asm volatile("cp.async.cg.shared.global [%0], [%1], 16;"::"r"(s),"l"(g));
}
__device__ __forceinline__ void cp_commit(){
    asm volatile("cp.async.commit_group;":::"memory");
}
__device__ __forceinline__ void ldm4(uint32_t* r, uint32_t a){
    asm volatile("ldmatrix.sync.aligned.m8n8.x4.shared.b16 {%0,%1,%2,%3}, [%4];"
        : "=r"(r[0]),"=r"(r[1]),"=r"(r[2]),"=r"(r[3]) : "r"(a));
}
__device__ __forceinline__ void mma16816f(float* c, const uint32_t* a, uint32_t b0, uint32_t b1){
    asm volatile("mma.sync.aligned.m16n8k16.row.col.f32.f16.f16.f32 "
        "{%0,%1,%2,%3},{%4,%5,%6,%7},{%8,%9},{%0,%1,%2,%3};"
        : "+f"(c[0]),"+f"(c[1]),"+f"(c[2]),"+f"(c[3])
        : "r"(a[0]),"r"(a[1]),"r"(a[2]),"r"(a[3]), "r"(b0),"r"(b1));
}
#define SWZ(o) ((o) ^ (((o) >> 3) & 0x70))
#define SSTG 32768u

#define WARP_SETUP() \
    int wm = wid >> 2, wn = wid & 3; \
    int rowA = (wm << 6) + (lane & 15); \
    int rowB = (wn << 5) + (lane & 15); \
    uint32_t sA = rowA & 7, sB = rowB & 7, cq = lane >> 4; \
    uint32_t aB[4], bB[2]; \
    _Pragma("unroll") for (int mi = 0; mi < 4; mi++) aB[mi] = (uint32_t)(rowA + (mi<<4)) * 128; \
    _Pragma("unroll") for (int nj = 0; nj < 2; nj++) bB[nj] = (uint32_t)(rowB + (nj<<4)) * 128; \
    float acc[4][4][4]; \
    _Pragma("unroll") for (int mi = 0; mi < 4; mi++) \
        _Pragma("unroll") for (int ni = 0; ni < 4; ni++) \
            _Pragma("unroll") for (int e2 = 0; e2 < 4; e2++) acc[mi][ni][e2] = 0.f;

#define MMA_CHUNK_1T(stgbase) do{ \
    _Pragma("unroll") \
    for (int ks = 0; ks < 4; ks++){ \
        uint32_t ah[4][4], bh[2][4]; \
        uint32_t ca = ((((ks<<1)|cq) ^ sA) << 4); \
        uint32_t cb = ((((ks<<1)|cq) ^ sB) << 4); \
        _Pragma("unroll") \
        for (int mi = 0; mi < 4; mi++) ldm4(ah[mi], (stgbase) + aB[mi] + ca); \
        _Pragma("unroll") \
        for (int nj = 0; nj < 2; nj++) ldm4(bh[nj], (stgbase) + bB[nj] + cb + 16384); \
        _Pragma("unroll") \
        for (int mi = 0; mi < 4; mi++) \
            _Pragma("unroll") \
            for (int ni = 0; ni < 4; ni++){ \
                uint32_t g = ni >> 1, s = ni & 1; \
                mma16816f(acc[mi][ni], ah[mi], bh[g][s], bh[g][s+2]); \
            } \
    } \
}while(0)

// K-loop: double-buffered cp.async pipeline over K chunks of 64
#define PIPELINE_K(NCH, ALOAD, BLOAD) \
    { \
        _Pragma("unroll") \
        for (int i = 0; i < 4; i++){ ALOAD(sb, i, 0); BLOAD(sb, i, 0); } \
        cp_commit(); \
    } \
    for (int c = 0; c < (NCH); c++){ \
        if (c + 1 < (NCH)){ \
            uint32_t sp_ = sb + ((c+1)&1)*SSTG; \
            size_t k0 = (size_t)(c+1) << 6; \
            _Pragma("unroll") \
            for (int i = 0; i < 4; i++){ ALOAD(sp_, i, k0); BLOAD(sp_, i, k0); } \
            cp_commit(); \
            asm volatile("cp.async.wait_group 1;":::"memory"); \
        } else { \
            asm volatile("cp.async.wait_group 0;":::"memory"); \
        } \
        __syncthreads(); \
        MMA_CHUNK_1T(sb + (c & 1)*SSTG); \
        __syncthreads(); \
    }

// ------------------------------- single-term fp16 GEMM -----------------------
// C[m,n] = act( sum_k A[m,k]*W[n,k] + bias[n] + R[m,n] )
// If C16b != null: merged mode; column block j = n>>9 routes to {C16,C16b,C16c}[j].
__global__ void __launch_bounds__(256,2)
gemm_s(const __half* __restrict__ A, const __half* __restrict__ W,
       const float* __restrict__ bias, const float* __restrict__ R,
       float* Cf, __half* C16, __half* C16b, __half* C16c,
       int N, int K, int relu)
{
    extern __shared__ char smem[];
    uint32_t sb = smem_u32(smem);
    int tid = threadIdx.x, wid = tid >> 5, lane = tid & 31;
    int m0 = blockIdx.y << 7, n0 = blockIdx.x << 7;

    size_t aoff[4], boff[4];
    uint32_t soff[4];
    #pragma unroll
    for (int i = 0; i < 4; i++){
        int idx = tid + (i << 8);
        int r = idx >> 3, u = idx & 7;
        aoff[i] = (size_t)(m0 + r) * K + u * 8;
        boff[i] = (size_t)(n0 + r) * K + u * 8;
        soff[i] = SWZ((uint32_t)(r * 128 + u * 16));
    }
    WARP_SETUP();

    #define AL_(sp,i,k0) cp16((sp) + soff[i],         A + aoff[i] + (k0))
    #define BL_(sp,i,k0) cp16((sp) + 16384 + soff[i], W + boff[i] + (k0))
    int nch = K >> 6;
    PIPELINE_K(nch, AL_, BL_);
    #undef AL_
    #undef BL_

    int gm = m0 + (wm << 6) + (lane >> 2);
    int gn = n0 + (wn << 5) + ((lane & 3) << 1);
    #pragma unroll
    for (int mi = 0; mi < 4; mi++)
        #pragma unroll
        for (int ni = 0; ni < 4; ni++)
            #pragma unroll
            for (int hh = 0; hh < 2; hh++){
                int rr = gm + (mi << 4) + hh * 8;
                int cc = gn + (ni << 3);
                float v0 = acc[mi][ni][hh*2+0];
                float v1 = acc[mi][ni][hh*2+1];
                if (bias){ v0 += bias[cc]; v1 += bias[cc+1]; }
                if (C16b){
                    int j = cc >> 9, c2 = cc & 511;
                    __half* dst = (j == 0) ? C16 : ((j == 1) ? C16b : C16c);
                    *reinterpret_cast<__half2*>(dst + (size_t)rr * 512 + c2) =
                        __floats2half2_rn(v0, v1);
                } else {
                    size_t o = (size_t)rr * N + cc;
                    if (R){ float2 r2 = *reinterpret_cast<const float2*>(R + o); v0 += r2.x; v1 += r2.y; }
                    if (relu){ v0 = fmaxf(v0, 0.f); v1 = fmaxf(v1, 0.f); }
                    if (Cf)  *reinterpret_cast<float2*>(Cf + o)  = make_float2(v0, v1);
                    if (C16) *reinterpret_cast<__half2*>(C16 + o) = __floats2half2_rn(v0, v1);
                }
            }
}

// ------------------- batched 512x512x512 weight-product GEMM -----------------
// z = stage*2 + kind.  kind0: M = WqT·(WkT)^T = Wq^T·Wk.  kind1: Wvo = Wo·Wv.
__global__ void __launch_bounds__(256,2)
gemm_w(const __half* __restrict__ wtt, const __half* __restrict__ wfp,
       __half* __restrict__ wmv)
{
    extern __shared__ char smem[];
    uint32_t sb = smem_u32(smem);
    int tid = threadIdx.x, wid = tid >> 5, lane = tid & 31;
    int z = blockIdx.z, stage = z >> 1, kind = z & 1;
    const __half* A = kind ? wfp + (size_t)(stage*4+3)*DDW : wtt + (size_t)(stage*3+0)*DDW;
    const __half* W = kind ? wtt + (size_t)(stage*3+2)*DDW : wtt + (size_t)(stage*3+1)*DDW;
    __half* C = wmv + (size_t)(stage*2+kind)*DDW;
    int m0 = blockIdx.y << 7, n0 = blockIdx.x << 7;

    size_t aoff[4], boff[4];
    uint32_t soff[4];
    #pragma unroll
    for (int i = 0; i < 4; i++){
        int idx = tid + (i << 8);
        int r = idx >> 3, u = idx & 7;
        aoff[i] = (size_t)(m0 + r) * 512 + u * 8;
        boff[i] = (size_t)(n0 + r) * 512 + u * 8;
        soff[i] = SWZ((uint32_t)(r * 128 + u * 16));
    }
    WARP_SETUP();

    #define AL_(sp,i,k0) cp16((sp) + soff[i],         A + aoff[i] + (k0))
    #define BL_(sp,i,k0) cp16((sp) + 16384 + soff[i], W + boff[i] + (k0))
    PIPELINE_K(8, AL_, BL_);
    #undef AL_
    #undef BL_

    int gm = m0 + (wm << 6) + (lane >> 2);
    int gn = n0 + (wn << 5) + ((lane & 3) << 1);
    #pragma unroll
    for (int mi = 0; mi < 4; mi++)
        #pragma unroll
        for (int ni = 0; ni < 4; ni++)
            #pragma unroll
            for (int hh = 0; hh < 2; hh++){
                int rr = gm + (mi << 4) + hh * 8;
                int cc = gn + (ni << 3);
                *reinterpret_cast<__half2*>(C + (size_t)rr * 512 + cc) =
                    __floats2half2_rn(acc[mi][ni][hh*2+0], acc[mi][ni][hh*2+1]);
            }
}

// --------------------------- fused token-embed (single-term) -----------------
__global__ void __launch_bounds__(256,2)
embed_f16(const __half* __restrict__ A, const __half* __restrict__ B,
          float* Cf, __half* Ch)
{
    extern __shared__ char smem[];
    uint32_t sb = smem_u32(smem);
    int tid = threadIdx.x, wid = tid >> 5, lane = tid & 31;
    int m0 = blockIdx.y << 7, n0 = blockIdx.x << 7;

    size_t aoff0[4], boff[4];
    int dm1[4], dp1[4];
    uint32_t soff[4];
    #pragma unroll
    for (int i = 0; i < 4; i++){
        int idx = tid + (i << 8);
        int r = idx >> 3, u = idx & 7;
        int am = m0 + r;
        int b = am / NL;
        int t = am - b * NL;
        aoff0[i] = (size_t)am * ND + u * 8;
        dm1[i] = ((t == 0    ? NL - 1 : t - 1) - t) * ND;
        dp1[i] = ((t == NL-1 ? 0      : t + 1) - t) * ND;
        boff[i] = (size_t)(n0 + r) * ND + u * 8;
        soff[i] = SWZ((uint32_t)(r * 128 + u * 16));
    }
    WARP_SETUP();

    #define ELOAD(stage, c_) do{ \
        int tap_ = (c_) >> 3; \
        int kb_ = ((c_) & 7) << 6; \
        size_t bo_ = (size_t)tap_ * DDW + kb_; \
        uint32_t sp_ = sb + (stage)*SSTG; \
        _Pragma("unroll") \
        for (int i_ = 0; i_ < 4; i_++){ \
            long ao_ = (long)aoff0[i_] + (tap_ == 0 ? dm1[i_] : (tap_ == 2 ? dp1[i_] : 0)) + kb_; \
            cp16(sp_ + soff[i_],          A + ao_); \
            cp16(sp_ + 16384 + soff[i_],  B + boff[i_] + bo_); \
        } \
        cp_commit(); \
    }while(0)

    ELOAD(0, 0);
    for (int c = 0; c < 24; c++){
        if (c + 1 < 24){
            ELOAD((c+1)&1, c+1);
            asm volatile("cp.async.wait_group 1;":::"memory");
        } else {
            asm volatile("cp.async.wait_group 0;":::"memory");
        }
        __syncthreads();
        MMA_CHUNK_1T(sb + (c & 1)*SSTG);
        __syncthreads();
    }
    #undef ELOAD

    int gm = m0 + (wm << 6) + (lane >> 2);
    int gn = n0 + (wn << 5) + ((lane & 3) << 1);
    #pragma unroll
    for (int mi = 0; mi < 4; mi++)
        #pragma unroll
        for (int ni = 0; ni < 4; ni++)
            #pragma unroll
            for (int hh = 0; hh < 2; hh++){
                int rr = gm + (mi << 4) + hh * 8;
                int cc = gn + (ni << 3);
                float v0 = acc[mi][ni][hh*2+0];
                float v1 = acc[mi][ni][hh*2+1];
                size_t o = (size_t)rr * ND + cc;
                if (Cf) *reinterpret_cast<float2*>(Cf + o) = make_float2(v0, v1);
                if (Ch) *reinterpret_cast<__half2*>(Ch + o) = __floats2half2_rn(v0, v1);
            }
}

// --------------------------- correlation (fp16, 1-term) ----------------------
__global__ void __launch_bounds__(256,2)
corr_f16(const __half* __restrict__ Qf, const __half* __restrict__ Kf)
{
    extern __shared__ char smem[];
    uint32_t sb = smem_u32(smem);
    int tid = threadIdx.x, wid = tid >> 5, lane = tid & 31;
    int bb = blockIdx.z;
    size_t base = (size_t)bb * NL * ND;
    int m0 = blockIdx.y << 7, n0 = blockIdx.x << 7;

    size_t aoff[4], boff[4];
    uint32_t soff[4];
    #pragma unroll
    for (int i = 0; i < 4; i++){
        int idx = tid + (i << 8);
        int r = idx >> 3, u = idx & 7;
        aoff[i] = base + (size_t)(m0 + r) * ND + u * 8;
        boff[i] = base + (size_t)(n0 + r) * ND + u * 8;
        soff[i] = SWZ((uint32_t)(r * 128 + u * 16));
    }
    WARP_SETUP();

    #define AL_(sp,i,k0) cp16((sp) + soff[i],         Qf + aoff[i] + (k0))
    #define BL_(sp,i,k0) cp16((sp) + 16384 + soff[i], Kf + boff[i] + (k0))
    PIPELINE_K(8, AL_, BL_);
    #undef AL_
    #undef BL_

    float* bins = reinterpret_cast<float*>(smem);
    if (tid < 255) bins[tid] = 0.f;
    __syncthreads();

    int lm = (wm << 6) + (lane >> 2);
    int ln = (wn << 5) + ((lane & 3) << 1);
    #pragma unroll
    for (int mi = 0; mi < 4; mi++)
        #pragma unroll
        for (int ni = 0; ni < 4; ni++)
            #pragma unroll
            for (int hh = 0; hh < 2; hh++){
                int rr = lm + (mi << 4) + hh * 8;
                int cc = ln + (ni << 3);
                atomicAdd(&bins[rr - cc + 127],     acc[mi][ni][hh*2+0]);
                atomicAdd(&bins[rr - cc - 1 + 127], acc[mi][ni][hh*2+1]);
            }
    __syncthreads();
    if (tid < 255){
        int tau = m0 - n0 + tid - 127;
        tau %= NL; if (tau < 0) tau += NL;
        atomicAdd(&g_mean[bb * NL + tau], bins[tid] * (1.f / 512.f));
    }
}

// ------------------------------ small kernels --------------------------------
__global__ void cvt_f16s(const float* __restrict__ x, __half* __restrict__ o, int n4)
{
    int i = blockIdx.x * blockDim.x + threadIdx.x;
    if (i >= n4) return;
    float4 v = reinterpret_cast<const float4*>(x)[i];
    __half2* op = reinterpret_cast<__half2*>(o);
    op[2*i]   = __floats2half2_rn(v.x, v.y);
    op[2*i+1] = __floats2half2_rn(v.z, v.w);
}

__global__ void cvt_proj_f16(const float* __restrict__ src, __half* __restrict__ h)
{
    int e = blockIdx.x * blockDim.x + threadIdx.x;
    if (e >= DDW) return;
    int n = e >> 9, k = e & 511;
    h[e] = __float2half_rn(src[n * 1536 + k * 3]);
}

// batched 512x512 fp32 -> fp16 transpose of Wq/Wk/Wv for 3 stages (z = stage*3 + which)
__global__ void transpose_w9(const float* __restrict__ w1, const float* __restrict__ w2,
                             const float* __restrict__ w3, __half* __restrict__ dst)
{
    __shared__ float tile[32][33];
    int z = blockIdx.z;
    int stage = z / 3, which = z - stage * 3;
    const float* src = (stage == 0 ? w1 : (stage == 1 ? w2 : w3)) + (size_t)which * DDW;
    __half* d = dst + (size_t)z * DDW;
    int bx = blockIdx.x << 5, by = blockIdx.y << 5;
    int tx = threadIdx.x, ty = threadIdx.y;   // (32, 8)
    #pragma unroll
    for (int j = 0; j < 32; j += 8)
        tile[ty + j][tx] = src[(size_t)(by + ty + j) * 512 + bx + tx];
    __syncthreads();
    #pragma unroll
    for (int j = 0; j < 32; j += 8)
        d[(size_t)(bx + ty + j) * 512 + by + tx] = __float2half_rn(tile[tx][ty + j]);
}

// batched merged-bias: grid (16, 3); warp-per-row coalesced reduction.
// b1024[s][0..511] = 0 ; b1024[s][512+n] = bo[n] + sum_e Wo[n,e]*bv[e]
__global__ void mkbias3(const float* __restrict__ w1, const float* __restrict__ w2,
                        const float* __restrict__ w3,
                        const float* __restrict__ b1, const float* __restrict__ b2,
                        const float* __restrict__ b3,
                        float* __restrict__ b1024)
{
    int s = blockIdx.y;
    const float* Wsel = (s == 0 ? w1 : (s == 1 ? w2 : w3));
    const float* bsel = (s == 0 ? b1 : (s == 1 ? b2 : b3));
    const float* Wo = Wsel + 3*DDW;
    const float* bv = bsel + 2*ND;
    const float* bo = bsel + 3*ND;
    float* bout = b1024 + s * 1024;
    int tid = threadIdx.x, wid = tid >> 5, lane = tid & 31;   // 256 thr = 8 warps

    if (tid < 32) bout[blockIdx.x * 32 + tid] = 0.f;

    #pragma unroll
    for (int i = 0; i < 4; i++){
        int n = blockIdx.x * 32 + wid * 4 + i;
        const float* row = Wo + (size_t)n * 512;
        float sum = 0.f;
        #pragma unroll
        for (int j = 0; j < 16; j++)
            sum += row[lane + j * 32] * bv[lane + j * 32];
        #pragma unroll
        for (int off = 16; off > 0; off >>= 1)
            sum += __shfl_down_sync(0xffffffff, sum, off);
        if (lane == 0) bout[512 + n] = sum + bo[n];
    }
}

__global__ void topk_kernel()
{
    __shared__ float gv[NL];
    __shared__ float rv[512];
    __shared__ int   ri[512];
    __shared__ int   sidx[NTOPK];
    int tid = threadIdx.x;
    for (int t = tid; t < NL; t += 512) {
        float s = 0.f;
        for (int b = 0; b < NB; b++) s += g_mean[b * NL + t];
        gv[t] = s;
    }
    __syncthreads();
    for (int it = 0; it < NTOPK; it++) {
        float bv = -INFINITY; int bi = 0x7fffffff;
        for (int t = tid; t < NL; t += 512) {
            float v = gv[t];
            if (v > bv || (v == bv && t < bi)) { bv = v; bi = t; }
        }
        rv[tid] = bv; ri[tid] = bi;
        __syncthreads();
        for (int s = 256; s > 0; s >>= 1) {
            if (tid < s) {
                if (rv[tid+s] > rv[tid] || (rv[tid+s] == rv[tid] && ri[tid+s] < ri[tid])) {
                    rv[tid] = rv[tid+s]; ri[tid] = ri[tid+s];
                }
            }
            __syncthreads();
        }
        if (tid == 0) { sidx[it] = ri[0]; gv[ri[0]] = -INFINITY; }
        __syncthreads();
    }
    if (tid < NTOPK) g_idx[tid] = sidx[tid];
    if (tid < NB) {
        float vals[NTOPK];
        float mx = -INFINITY;
        for (int i = 0; i < NTOPK; i++) {
            vals[i] = g_mean[tid * NL + sidx[i]];
            mx = fmaxf(mx, vals[i]);
        }
        float s = 0.f;
        for (int i = 0; i < NTOPK; i++) { vals[i] = expf(vals[i] - mx); s += vals[i]; }
        float inv = 1.f / s;
        for (int i = 0; i < NTOPK; i++) g_wt[tid * NTOPK + i] = vals[i] * inv;
    }
}

// time-delay aggregation + residual: Of = R + sum_i w_i * V'(t+delta_i)
__global__ void roll_kernel(const __half* __restrict__ V16, const float* __restrict__ R,
                            float* __restrict__ Of, __half* __restrict__ O16)
{
    int e = blockIdx.x * blockDim.x + threadIdx.x;
    if (e >= NBLD/2) return;
    int dh = e & 255;
    int row = e >> 8;
    int b = row / NL;
    int t = row - b * NL;
    float2 r2 = *reinterpret_cast<const float2*>(R + (size_t)row * ND + dh*2);
    float sx = r2.x, sy = r2.y;
    #pragma unroll
    for (int i = 0; i < NTOPK; i++) {
        int tt = t + g_idx[i];
        if (tt >= NL) tt -= NL;
        __half2 v = *reinterpret_cast<const __half2*>(V16 + ((size_t)(b*NL + tt))*ND + dh*2);
        float2 vf = __half22float2(v);
        float w = g_wt[b * NTOPK + i];
        sx += w * vf.x; sy += w * vf.y;
    }
    *reinterpret_cast<float2*>(Of + (size_t)row * ND + dh*2) = make_float2(sx, sy);
    if (O16)
        *reinterpret_cast<__half2*>(O16 + (size_t)row * ND + dh*2) = __floats2half2_rn(sx, sy);
}

__global__ void decomp_kernel(const float* __restrict__ X, float* __restrict__ Of,
                              __half* O16)
{
    int i = blockIdx.x * blockDim.x + threadIdx.x;
    if (i >= NBLD/8) return;
    int d = i & 511;
    int c = i >> 9;
    int b = c / (NL/8);
    int tb = (c - b * (NL/8)) * 8;
    const float* Xb = X + (size_t)b * NL * ND + d;

    float acc = 0.f;
    #pragma unroll
    for (int u = -12; u <= 12; u++){
        int t = tb + u;
        t = t < 0 ? 0 : (t >= NL ? NL - 1 : t);
        acc += Xb[(size_t)t * ND];
    }
    #pragma unroll
    for (int j = 0; j < 8; j++){
        int t = tb + j;
        float x = Xb[(size_t)t * ND];
        float v = x - acc * (1.f / 25.f);
        size_t e = ((size_t)b * NL + t) * ND + d;
        if (Of)  Of[e]  = v;
        if (O16) O16[e] = __float2half_rn(v);
        int ta = t + 13; ta = ta >= NL ? NL - 1 : ta;
        int ts = t - 12; ts = ts < 0 ? 0 : ts;
        acc += Xb[(size_t)ta * ND] - Xb[(size_t)ts * ND];
    }
}

// ------------------------------- host side -----------------------------------
#define GETSYM(var, sym) do{ cudaGetSymbolAddress((void**)&var, sym); }while(0)

extern "C" void kernel_launch(void* const* d_in, const int* in_sizes, int n_in,
                              void* d_out, int out_size)
{
    const float* x_s      = (const float*)d_in[0];
    const float* x_w      = (const float*)d_in[1];
    const float* wc1_W    = (const float*)d_in[2];
    const float* wc1_b    = (const float*)d_in[3];
    const float* wc2_W    = (const float*)d_in[4];
    const float* wc2_b    = (const float*)d_in[5];
    const float* attn_W   = (const float*)d_in[6];
    const float* attn_b   = (const float*)d_in[7];
    const float* wc1_proj = (const float*)d_in[8];
    const float* wc2_proj = (const float*)d_in[9];
    const float* conv1_W  = (const float*)d_in[10];
    const float* conv2_W  = (const float*)d_in[11];
    float* out  = (float*)d_out;
    float* out2 = out + NBLD;

    float *pxs, *pxs2, *ptmp, *pv32, *pmean, *pb1024;
    GETSYM(pxs, g_xs); GETSYM(pxs2, g_xs2); GETSYM(ptmp, g_tmp);
    GETSYM(pv32, g_v32); GETSYM(pmean, g_mean); GETSYM(pb1024, g_b1024);
    __half *wf, *pweh, *pwmv, *pwtt;
    GETSYM(wf, g_wf); GETSYM(pweh, g_weh); GETSYM(pwmv, g_wmv); GETSYM(pwtt, g_wtt);
    __half *pfXW,*pfXSI,*pfK,*pfV,*pfXSa,*pfXS2,*pfXW1,*pfXSB,*pfH;
    GETSYM(pfXW, fXW);   GETSYM(pfXSI, fXSI);
    GETSYM(pfK, fK);     GETSYM(pfV, fV);
    GETSYM(pfXSa, fXSa); GETSYM(pfXS2, fXS2);
    GETSYM(pfXW1, fXW1); GETSYM(pfXSB, fXSB); GETSYM(pfH, fH);

    cudaFuncSetAttribute(gemm_s,    cudaFuncAttributeMaxDynamicSharedMemorySize, 2*SSTG);
    cudaFuncSetAttribute(gemm_w,    cudaFuncAttributeMaxDynamicSharedMemorySize, 2*SSTG);
    cudaFuncSetAttribute(embed_f16, cudaFuncAttributeMaxDynamicSharedMemorySize, 2*SSTG);
    cudaFuncSetAttribute(corr_f16,  cudaFuncAttributeMaxDynamicSharedMemorySize, 2*SSTG);

    const int nRB = (NBLD/2 + 255) / 256;
    const int nDB = (NBLD/8 + 255) / 256;
    dim3 corrG(12, 12, NB);
    dim3 embG(4, 192);

    // plain GEMM over all tokens
    auto G = [&](const __half* A, int woff, const float* bias, const float* R,
                 float* Cf, __half* C16, int N, int K, int relu){
        dim3 g(N >> 7, MTOT >> 7);
        gemm_s<<<g, 256, 2*SSTG>>>(A, wf + (size_t)woff * DDW, bias, R,
                                   Cf, C16, nullptr, nullptr, N, K, relu);
    };
    // merged [k~ | v'] GEMM: N=1024, routed outputs
    auto Gm = [&](const __half* A, int stage){
        dim3 g(8, MTOT >> 7);
        gemm_s<<<g, 256, 2*SSTG>>>(A, pwmv + (size_t)stage * 2 * DDW,
                                   pb1024 + stage * 1024, nullptr,
                                   nullptr, pfK, pfV, pfV, 1024, ND, 0);
    };

    // ---- weight conversions -------------------------------------------------
    cvt_f16s<<<1024,256>>>(wc1_W,  wf +  0*(size_t)DDW, DDW);
    cvt_f16s<<<1024,256>>>(attn_W, wf +  4*(size_t)DDW, DDW);
    cvt_f16s<<<1024,256>>>(wc2_W,  wf +  8*(size_t)DDW, DDW);
    cvt_f16s<<<1024,256>>>(conv1_W,wf + 12*(size_t)DDW, DDW);
    cvt_f16s<<<1024,256>>>(conv2_W,wf + 16*(size_t)DDW, DDW);
    for (int j = 0; j < 3; j++){
        cvt_proj_f16<<<(DDW+255)/256,256>>>(wc1_proj + j, pweh + (size_t)j*DDW);
        cvt_proj_f16<<<(DDW+255)/256,256>>>(wc2_proj + j, pweh + (size_t)(3+j)*DDW);
    }
    cvt_f16s<<<(NBLD/4+255)/256,256>>>(x_w, pfXW,  NBLD/4);
    cvt_f16s<<<(NBLD/4+255)/256,256>>>(x_s, pfXSI, NBLD/4);

    // ---- folded weight products (batched prologue) --------------------------
    {
        dim3 trG(16, 16, 9), trB(32, 8);
        transpose_w9<<<trG, trB>>>(wc1_W, attn_W, wc2_W, pwtt);
        dim3 wg(4, 4, 6);
        gemm_w<<<wg, 256, 2*SSTG>>>(pwtt, wf, pwmv);
        dim3 mbG(16, 3);
        mkbias3<<<mbG, 256>>>(wc1_W, attn_W, wc2_W, wc1_b, attn_b, wc2_b, pb1024);
    }

    // ---- stage A: x_s += attn(q=x_w, k=v=x_s, wc1) --------------------------
    Gm(pfXSI, 0);
    cudaMemsetAsync(pmean, 0, NB*NL*sizeof(float), 0);
    corr_f16<<<corrG, 256, 2*SSTG>>>(pfXW, pfK);
    topk_kernel<<<1, 512>>>();
    roll_kernel<<<nRB, 256>>>(pfV, x_s, pxs, pfXSa);

    // ---- stage B: xw1 = token_embed(x_w, wc1_proj) --------------------------
    embed_f16<<<embG, 256, 2*SSTG>>>(pfXW, pweh, nullptr, pfXW1);

    // ---- stage C: xs += attn(xs, xs, xs, attn_W) ----------------------------
    Gm(pfXSa, 1);
    cudaMemsetAsync(pmean, 0, NB*NL*sizeof(float), 0);
    corr_f16<<<corrG, 256, 2*SSTG>>>(pfXSa, pfK);
    topk_kernel<<<1, 512>>>();
    roll_kernel<<<nRB, 256>>>(pfV, pxs, pxs, nullptr);

    // ---- stage D: xs2 = series_decomp(xs) -----------------------------------
    decomp_kernel<<<nDB, 256>>>(pxs, pxs2, pfXS2);

    // ---- stage E: xs2' = xs2 + attn(q=xw1, k=v=xs2, wc2) --------------------
    Gm(pfXS2, 2);
    cudaMemsetAsync(pmean, 0, NB*NL*sizeof(float), 0);
    corr_f16<<<corrG, 256, 2*SSTG>>>(pfXW1, pfK);
    topk_kernel<<<1, 512>>>();
    roll_kernel<<<nRB, 256>>>(pfV, pxs2, ptmp, pfXSB);

    // ---- stage F: x_w_new = token_embed(xw1, wc2_proj) -> out2 --------------
    embed_f16<<<embG, 256, 2*SSTG>>>(pfXW1, pweh + 3*(size_t)DDW, out2, nullptr);

    // ---- stage G: FFN + final series_decomp -> out --------------------------
    G(pfXSB, 12, nullptr, nullptr, nullptr, pfH, NDFF, ND,   1);
    G(pfH,   16, nullptr, ptmp,    pv32,    nullptr, ND, NDFF, 0);
    decomp_kernel<<<nDB, 256>>>(pv32, out, nullptr);
}

// round 15
// speedup vs baseline: 1.2874x; 1.0174x over previous
#include <cuda_runtime.h>
#include <cuda_fp16.h>
#include <cstdint>
#include <math.h>

#define NB    16
#define NL    1536
#define ND    512
#define NDFF  2048
#define NTOPK 7
#define NBLD  (NB*NL*ND)
#define NH    (NB*NL*NDFF)
#define DDW   262144            // 512*512
#define MTOT  (NB*NL)           // 24576

// ------------------------------- scratch ------------------------------------
__device__ float g_xs[NBLD];
__device__ float g_xs2[NBLD];
__device__ float g_tmp[NBLD];
__device__ float g_v32[NBLD];
__device__ float g_mean[NB*NL];
__device__ int   g_idx[NTOPK];
__device__ float g_wt[NB*NTOPK];
__device__ float g_b1024[3*1024];   // merged-GEMM bias per stage: [0]*512 ++ bfull

// fp16 arenas
__device__ __half g_wf[20*DDW];   // wc1(4) attn(4) wc2(4) conv1(4) conv2(4)
__device__ __half g_weh[6*DDW];   // embed weights (wc1_proj 0-2, wc2_proj 3-5)
__device__ __half g_wmv[6*DDW];   // per stage: [M ; Wvo]
__device__ __half g_wtt[9*DDW];   // transposed Wq/Wk/Wv per stage
__device__ __half fXW[NBLD];
__device__ __half fXSI[NBLD];
__device__ __half fK[NBLD], fV[NBLD];
__device__ __half fXSa[NBLD], fXS2[NBLD];
__device__ __half fXW1[NBLD];
__device__ __half fXSB[NBLD];
__device__ __half fH[NH];

// ------------------------------- helpers -------------------------------------
__device__ __forceinline__ uint32_t smem_u32(const void* p){
    uint32_t a;
    asm("{ .reg .u64 t; cvta.to.shared.u64 t, %1; cvt.u32.u64 %0, t; }":"=r"(a):"l"(p));
    return a;
}
__device__ __forceinline__ void cp16(uint32_t s, const void* g){
    asm volatile("cp.async.cg.shared.global [%0], [%1], 16;"::"r"(s),"l"(g));
}
__device__ __forceinline__ void cp_commit(){
    asm volatile("cp.async.commit_group;":::"memory");
}
__device__ __forceinline__ void ldm4(uint32_t* r, uint32_t a){
    asm volatile("ldmatrix.sync.aligned.m8n8.x4.shared.b16 {%0,%1,%2,%3}, [%4];"
        : "=r"(r[0]),"=r"(r[1]),"=r"(r[2]),"=r"(r[3]) : "r"(a));
}
__device__ __forceinline__ void mma16816f(float* c, const uint32_t* a, uint32_t b0, uint32_t b1){
    asm volatile("mma.sync.aligned.m16n8k16.row.col.f32.f16.f16.f32 "
        "{%0,%1,%2,%3},{%4,%5,%6,%7},{%8,%9},{%0,%1,%2,%3};"
        : "+f"(c[0]),"+f"(c[1]),"+f"(c[2]),"+f"(c[3])
        : "r"(a[0]),"r"(a[1]),"r"(a[2]),"r"(a[3]), "r"(b0),"r"(b1));
}
// fp16-accumulator variant: c = 2 regs (half2 row r ; half2 row r+8)
__device__ __forceinline__ void mma16816h(uint32_t* c, const uint32_t* a, uint32_t b0, uint32_t b1){
    asm volatile("mma.sync.aligned.m16n8k16.row.col.f16.f16.f16.f16 "
        "{%0,%1},{%2,%3,%4,%5},{%6,%7},{%0,%1};"
        : "+r"(c[0]),"+r"(c[1])
        : "r"(a[0]),"r"(a[1]),"r"(a[2]),"r"(a[3]), "r"(b0),"r"(b1));
}
#define SWZ(o) ((o) ^ (((o) >> 3) & 0x70))
#define SSTG 32768u

#define WARP_SETUP() \
    int wm = wid >> 2, wn = wid & 3; \
    int rowA = (wm << 6) + (lane & 15); \
    int rowB = (wn << 5) + (lane & 15); \
    uint32_t sA = rowA & 7, sB = rowB & 7, cq = lane >> 4; \
    uint32_t aB[4], bB[2]; \
    _Pragma("unroll") for (int mi = 0; mi < 4; mi++) aB[mi] = (uint32_t)(rowA + (mi<<4)) * 128; \
    _Pragma("unroll") for (int nj = 0; nj < 2; nj++) bB[nj] = (uint32_t)(rowB + (nj<<4)) * 128;

#define ACC_F32() \
    float acc[4][4][4]; \
    _Pragma("unroll") for (int mi = 0; mi < 4; mi++) \
        _Pragma("unroll") for (int ni = 0; ni < 4; ni++) \
            _Pragma("unroll") for (int e2 = 0; e2 < 4; e2++) acc[mi][ni][e2] = 0.f;

#define MMA_CHUNK_1T(stgbase) do{ \
    _Pragma("unroll") \
    for (int ks = 0; ks < 4; ks++){ \
        uint32_t ah[4][4], bh[2][4]; \
        uint32_t ca = ((((ks<<1)|cq) ^ sA) << 4); \
        uint32_t cb = ((((ks<<1)|cq) ^ sB) << 4); \
        _Pragma("unroll") \
        for (int mi = 0; mi < 4; mi++) ldm4(ah[mi], (stgbase) + aB[mi] + ca); \
        _Pragma("unroll") \
        for (int nj = 0; nj < 2; nj++) ldm4(bh[nj], (stgbase) + bB[nj] + cb + 16384); \
        _Pragma("unroll") \
        for (int mi = 0; mi < 4; mi++) \
            _Pragma("unroll") \
            for (int ni = 0; ni < 4; ni++){ \
                uint32_t g = ni >> 1, s = ni & 1; \
                mma16816f(acc[mi][ni], ah[mi], bh[g][s], bh[g][s+2]); \
            } \
    } \
}while(0)

// fp16-acc version of the compute chunk
#define MMA_CHUNK_H(stgbase) do{ \
    _Pragma("unroll") \
    for (int ks = 0; ks < 4; ks++){ \
        uint32_t ah[4][4], bh[2][4]; \
        uint32_t ca = ((((ks<<1)|cq) ^ sA) << 4); \
        uint32_t cb = ((((ks<<1)|cq) ^ sB) << 4); \
        _Pragma("unroll") \
        for (int mi = 0; mi < 4; mi++) ldm4(ah[mi], (stgbase) + aB[mi] + ca); \
        _Pragma("unroll") \
        for (int nj = 0; nj < 2; nj++) ldm4(bh[nj], (stgbase) + bB[nj] + cb + 16384); \
        _Pragma("unroll") \
        for (int mi = 0; mi < 4; mi++) \
            _Pragma("unroll") \
            for (int ni = 0; ni < 4; ni++){ \
                uint32_t g = ni >> 1, s = ni & 1; \
                mma16816h(hacc[mi][ni], ah[mi], bh[g][s], bh[g][s+2]); \
            } \
    } \
}while(0)

// K-loop: double-buffered cp.async pipeline over K chunks of 64
#define PIPELINE_K(NCH, ALOAD, BLOAD, CHUNK) \
    { \
        _Pragma("unroll") \
        for (int i = 0; i < 4; i++){ ALOAD(sb, i, 0); BLOAD(sb, i, 0); } \
        cp_commit(); \
    } \
    for (int c = 0; c < (NCH); c++){ \
        if (c + 1 < (NCH)){ \
            uint32_t sp_ = sb + ((c+1)&1)*SSTG; \
            size_t k0 = (size_t)(c+1) << 6; \
            _Pragma("unroll") \
            for (int i = 0; i < 4; i++){ ALOAD(sp_, i, k0); BLOAD(sp_, i, k0); } \
            cp_commit(); \
            asm volatile("cp.async.wait_group 1;":::"memory"); \
        } else { \
            asm volatile("cp.async.wait_group 0;":::"memory"); \
        } \
        __syncthreads(); \
        CHUNK(sb + (c & 1)*SSTG); \
        __syncthreads(); \
    }

// ------------------------------- single-term fp16 GEMM -----------------------
// C[m,n] = act( sum_k A[m,k]*W[n,k] + bias[n] + R[m,n] )
// If C16b != null: merged mode; column block j = n>>9 routes to {C16,C16b,C16c}[j].
__global__ void __launch_bounds__(256,2)
gemm_s(const __half* __restrict__ A, const __half* __restrict__ W,
       const float* __restrict__ bias, const float* __restrict__ R,
       float* Cf, __half* C16, __half* C16b, __half* C16c,
       int N, int K, int relu)
{
    extern __shared__ char smem[];
    uint32_t sb = smem_u32(smem);
    int tid = threadIdx.x, wid = tid >> 5, lane = tid & 31;
    int m0 = blockIdx.y << 7, n0 = blockIdx.x << 7;

    size_t aoff[4], boff[4];
    uint32_t soff[4];
    #pragma unroll
    for (int i = 0; i < 4; i++){
        int idx = tid + (i << 8);
        int r = idx >> 3, u = idx & 7;
        aoff[i] = (size_t)(m0 + r) * K + u * 8;
        boff[i] = (size_t)(n0 + r) * K + u * 8;
        soff[i] = SWZ((uint32_t)(r * 128 + u * 16));
    }
    WARP_SETUP();
    ACC_F32();

    #define AL_(sp,i,k0) cp16((sp) + soff[i],         A + aoff[i] + (k0))
    #define BL_(sp,i,k0) cp16((sp) + 16384 + soff[i], W + boff[i] + (k0))
    int nch = K >> 6;
    PIPELINE_K(nch, AL_, BL_, MMA_CHUNK_1T);
    #undef AL_
    #undef BL_

    int gm = m0 + (wm << 6) + (lane >> 2);
    int gn = n0 + (wn << 5) + ((lane & 3) << 1);
    #pragma unroll
    for (int mi = 0; mi < 4; mi++)
        #pragma unroll
        for (int ni = 0; ni < 4; ni++)
            #pragma unroll
            for (int hh = 0; hh < 2; hh++){
                int rr = gm + (mi << 4) + hh * 8;
                int cc = gn + (ni << 3);
                float v0 = acc[mi][ni][hh*2+0];
                float v1 = acc[mi][ni][hh*2+1];
                if (bias){ v0 += bias[cc]; v1 += bias[cc+1]; }
                if (C16b){
                    int j = cc >> 9, c2 = cc & 511;
                    __half* dst = (j == 0) ? C16 : ((j == 1) ? C16b : C16c);
                    *reinterpret_cast<__half2*>(dst + (size_t)rr * 512 + c2) =
                        __floats2half2_rn(v0, v1);
                } else {
                    size_t o = (size_t)rr * N + cc;
                    if (R){ float2 r2 = *reinterpret_cast<const float2*>(R + o); v0 += r2.x; v1 += r2.y; }
                    if (relu){ v0 = fmaxf(v0, 0.f); v1 = fmaxf(v1, 0.f); }
                    if (Cf)  *reinterpret_cast<float2*>(Cf + o)  = make_float2(v0, v1);
                    if (C16) *reinterpret_cast<__half2*>(C16 + o) = __floats2half2_rn(v0, v1);
                }
            }
}

// ------------------- batched 512x512x512 weight-product GEMM -----------------
// z = stage*2 + kind.  kind0: M = Wq^T·Wk.  kind1: Wvo = Wo·Wv.
__global__ void __launch_bounds__(256,2)
gemm_w(const __half* __restrict__ wtt, const __half* __restrict__ wfp,
       __half* __restrict__ wmv)
{
    extern __shared__ char smem[];
    uint32_t sb = smem_u32(smem);
    int tid = threadIdx.x, wid = tid >> 5, lane = tid & 31;
    int z = blockIdx.z, stage = z >> 1, kind = z & 1;
    const __half* A = kind ? wfp + (size_t)(stage*4+3)*DDW : wtt + (size_t)(stage*3+0)*DDW;
    const __half* W = kind ? wtt + (size_t)(stage*3+2)*DDW : wtt + (size_t)(stage*3+1)*DDW;
    __half* C = wmv + (size_t)(stage*2+kind)*DDW;
    int m0 = blockIdx.y << 7, n0 = blockIdx.x << 7;

    size_t aoff[4], boff[4];
    uint32_t soff[4];
    #pragma unroll
    for (int i = 0; i < 4; i++){
        int idx = tid + (i << 8);
        int r = idx >> 3, u = idx & 7;
        aoff[i] = (size_t)(m0 + r) * 512 + u * 8;
        boff[i] = (size_t)(n0 + r) * 512 + u * 8;
        soff[i] = SWZ((uint32_t)(r * 128 + u * 16));
    }
    WARP_SETUP();
    ACC_F32();

    #define AL_(sp,i,k0) cp16((sp) + soff[i],         A + aoff[i] + (k0))
    #define BL_(sp,i,k0) cp16((sp) + 16384 + soff[i], W + boff[i] + (k0))
    PIPELINE_K(8, AL_, BL_, MMA_CHUNK_1T);
    #undef AL_
    #undef BL_

    int gm = m0 + (wm << 6) + (lane >> 2);
    int gn = n0 + (wn << 5) + ((lane & 3) << 1);
    #pragma unroll
    for (int mi = 0; mi < 4; mi++)
        #pragma unroll
        for (int ni = 0; ni < 4; ni++)
            #pragma unroll
            for (int hh = 0; hh < 2; hh++){
                int rr = gm + (mi << 4) + hh * 8;
                int cc = gn + (ni << 3);
                *reinterpret_cast<__half2*>(C + (size_t)rr * 512 + cc) =
                    __floats2half2_rn(acc[mi][ni][hh*2+0], acc[mi][ni][hh*2+1]);
            }
}

// --------------------------- fused token-embed (single-term) -----------------
__global__ void __launch_bounds__(256,2)
embed_f16(const __half* __restrict__ A, const __half* __restrict__ B,
          float* Cf, __half* Ch)
{
    extern __shared__ char smem[];
    uint32_t sb = smem_u32(smem);
    int tid = threadIdx.x, wid = tid >> 5, lane = tid & 31;
    int m0 = blockIdx.y << 7, n0 = blockIdx.x << 7;

    size_t aoff0[4], boff[4];
    int dm1[4], dp1[4];
    uint32_t soff[4];
    #pragma unroll
    for (int i = 0; i < 4; i++){
        int idx = tid + (i << 8);
        int r = idx >> 3, u = idx & 7;
        int am = m0 + r;
        int b = am / NL;
        int t = am - b * NL;
        aoff0[i] = (size_t)am * ND + u * 8;
        dm1[i] = ((t == 0    ? NL - 1 : t - 1) - t) * ND;
        dp1[i] = ((t == NL-1 ? 0      : t + 1) - t) * ND;
        boff[i] = (size_t)(n0 + r) * ND + u * 8;
        soff[i] = SWZ((uint32_t)(r * 128 + u * 16));
    }
    WARP_SETUP();
    ACC_F32();

    #define ELOAD(stage, c_) do{ \
        int tap_ = (c_) >> 3; \
        int kb_ = ((c_) & 7) << 6; \
        size_t bo_ = (size_t)tap_ * DDW + kb_; \
        uint32_t sp_ = sb + (stage)*SSTG; \
        _Pragma("unroll") \
        for (int i_ = 0; i_ < 4; i_++){ \
            long ao_ = (long)aoff0[i_] + (tap_ == 0 ? dm1[i_] : (tap_ == 2 ? dp1[i_] : 0)) + kb_; \
            cp16(sp_ + soff[i_],          A + ao_); \
            cp16(sp_ + 16384 + soff[i_],  B + boff[i_] + bo_); \
        } \
        cp_commit(); \
    }while(0)

    ELOAD(0, 0);
    for (int c = 0; c < 24; c++){
        if (c + 1 < 24){
            ELOAD((c+1)&1, c+1);
            asm volatile("cp.async.wait_group 1;":::"memory");
        } else {
            asm volatile("cp.async.wait_group 0;":::"memory");
        }
        __syncthreads();
        MMA_CHUNK_1T(sb + (c & 1)*SSTG);
        __syncthreads();
    }
    #undef ELOAD

    int gm = m0 + (wm << 6) + (lane >> 2);
    int gn = n0 + (wn << 5) + ((lane & 3) << 1);
    #pragma unroll
    for (int mi = 0; mi < 4; mi++)
        #pragma unroll
        for (int ni = 0; ni < 4; ni++)
            #pragma unroll
            for (int hh = 0; hh < 2; hh++){
                int rr = gm + (mi << 4) + hh * 8;
                int cc = gn + (ni << 3);
                float v0 = acc[mi][ni][hh*2+0];
                float v1 = acc[mi][ni][hh*2+1];
                size_t o = (size_t)rr * ND + cc;
                if (Cf) *reinterpret_cast<float2*>(Cf + o) = make_float2(v0, v1);
                if (Ch) *reinterpret_cast<__half2*>(Ch + o) = __floats2half2_rn(v0, v1);
            }
}

// --------------------------- correlation (fp16, f16-acc) ---------------------
__global__ void __launch_bounds__(256,2)
corr_f16(const __half* __restrict__ Qf, const __half* __restrict__ Kf)
{
    extern __shared__ char smem[];
    uint32_t sb = smem_u32(smem);
    int tid = threadIdx.x, wid = tid >> 5, lane = tid & 31;
    int bb = blockIdx.z;
    size_t base = (size_t)bb * NL * ND;
    int m0 = blockIdx.y << 7, n0 = blockIdx.x << 7;

    size_t aoff[4], boff[4];
    uint32_t soff[4];
    #pragma unroll
    for (int i = 0; i < 4; i++){
        int idx = tid + (i << 8);
        int r = idx >> 3, u = idx & 7;
        aoff[i] = base + (size_t)(m0 + r) * ND + u * 8;
        boff[i] = base + (size_t)(n0 + r) * ND + u * 8;
        soff[i] = SWZ((uint32_t)(r * 128 + u * 16));
    }
    WARP_SETUP();
    uint32_t hacc[4][4][2];
    #pragma unroll
    for (int mi = 0; mi < 4; mi++)
        #pragma unroll
        for (int ni = 0; ni < 4; ni++){ hacc[mi][ni][0] = 0u; hacc[mi][ni][1] = 0u; }

    #define AL_(sp,i,k0) cp16((sp) + soff[i],         Qf + aoff[i] + (k0))
    #define BL_(sp,i,k0) cp16((sp) + 16384 + soff[i], Kf + boff[i] + (k0))
    PIPELINE_K(8, AL_, BL_, MMA_CHUNK_H);
    #undef AL_
    #undef BL_

    float* bins = reinterpret_cast<float*>(smem);
    if (tid < 255) bins[tid] = 0.f;
    __syncthreads();

    int lm = (wm << 6) + (lane >> 2);
    int ln = (wn << 5) + ((lane & 3) << 1);
    #pragma unroll
    for (int mi = 0; mi < 4; mi++)
        #pragma unroll
        for (int ni = 0; ni < 4; ni++)
            #pragma unroll
            for (int hh = 0; hh < 2; hh++){
                int rr = lm + (mi << 4) + hh * 8;
                int cc = ln + (ni << 3);
                float2 vf = __half22float2(*reinterpret_cast<__half2*>(&hacc[mi][ni][hh]));
                atomicAdd(&bins[rr - cc + 127],     vf.x);
                atomicAdd(&bins[rr - cc - 1 + 127], vf.y);
            }
    __syncthreads();
    if (tid < 255){
        int tau = m0 - n0 + tid - 127;
        tau %= NL; if (tau < 0) tau += NL;
        atomicAdd(&g_mean[bb * NL + tau], bins[tid] * (1.f / 512.f));
    }
}

// ------------------------------ small kernels --------------------------------
// batched fp32 -> fp16 convert: up to 8 sources selected by grid.z
__global__ void cvt_f16s_b(const float* s0, const float* s1, const float* s2,
                           const float* s3, const float* s4,
                           __half* d0, __half* d1, __half* d2, __half* d3, __half* d4,
                           int n4)
{
    int z = blockIdx.z;
    const float* x = (z==0?s0:(z==1?s1:(z==2?s2:(z==3?s3:s4))));
    __half* o      = (z==0?d0:(z==1?d1:(z==2?d2:(z==3?d3:d4))));
    int i = blockIdx.x * blockDim.x + threadIdx.x;
    if (i >= n4) return;
    float4 v = reinterpret_cast<const float4*>(x)[i];
    __half2* op = reinterpret_cast<__half2*>(o);
    op[2*i]   = __floats2half2_rn(v.x, v.y);
    op[2*i+1] = __floats2half2_rn(v.z, v.w);
}

__global__ void cvt_proj_f16(const float* __restrict__ src1, const float* __restrict__ src2,
                             __half* __restrict__ h)
{
    int z = blockIdx.z;                 // 0..5
    const float* src = (z < 3 ? src1 + (z % 3) : src2 + (z % 3));
    __half* d = h + (size_t)z * DDW;
    int e = blockIdx.x * blockDim.x + threadIdx.x;
    if (e >= DDW) return;
    int n = e >> 9, k = e & 511;
    d[e] = __float2half_rn(src[n * 1536 + k * 3]);
}

// batched 512x512 fp32 -> fp16 transpose of Wq/Wk/Wv for 3 stages
__global__ void transpose_w9(const float* __restrict__ w1, const float* __restrict__ w2,
                             const float* __restrict__ w3, __half* __restrict__ dst)
{
    __shared__ float tile[32][33];
    int z = blockIdx.z;
    int stage = z / 3, which = z - stage * 3;
    const float* src = (stage == 0 ? w1 : (stage == 1 ? w2 : w3)) + (size_t)which * DDW;
    __half* d = dst + (size_t)z * DDW;
    int bx = blockIdx.x << 5, by = blockIdx.y << 5;
    int tx = threadIdx.x, ty = threadIdx.y;   // (32, 8)
    #pragma unroll
    for (int j = 0; j < 32; j += 8)
        tile[ty + j][tx] = src[(size_t)(by + ty + j) * 512 + bx + tx];
    __syncthreads();
    #pragma unroll
    for (int j = 0; j < 32; j += 8)
        d[(size_t)(bx + ty + j) * 512 + by + tx] = __float2half_rn(tile[tx][ty + j]);
}

// batched merged-bias: grid (16, 3); warp-per-row coalesced reduction.
__global__ void mkbias3(const float* __restrict__ w1, const float* __restrict__ w2,
                        const float* __restrict__ w3,
                        const float* __restrict__ b1, const float* __restrict__ b2,
                        const float* __restrict__ b3,
                        float* __restrict__ b1024)
{
    int s = blockIdx.y;
    const float* Wsel = (s == 0 ? w1 : (s == 1 ? w2 : w3));
    const float* bsel = (s == 0 ? b1 : (s == 1 ? b2 : b3));
    const float* Wo = Wsel + 3*DDW;
    const float* bv = bsel + 2*ND;
    const float* bo = bsel + 3*ND;
    float* bout = b1024 + s * 1024;
    int tid = threadIdx.x, wid = tid >> 5, lane = tid & 31;

    if (tid < 32) bout[blockIdx.x * 32 + tid] = 0.f;

    #pragma unroll
    for (int i = 0; i < 4; i++){
        int n = blockIdx.x * 32 + wid * 4 + i;
        const float* row = Wo + (size_t)n * 512;
        float sum = 0.f;
        #pragma unroll
        for (int j = 0; j < 16; j++)
            sum += row[lane + j * 32] * bv[lane + j * 32];
        #pragma unroll
        for (int off = 16; off > 0; off >>= 1)
            sum += __shfl_down_sync(0xffffffff, sum, off);
        if (lane == 0) bout[512 + n] = sum + bo[n];
    }
}

__global__ void topk_kernel()
{
    __shared__ float gv[NL];
    __shared__ float rv[512];
    __shared__ int   ri[512];
    __shared__ int   sidx[NTOPK];
    int tid = threadIdx.x;
    for (int t = tid; t < NL; t += 512) {
        float s = 0.f;
        for (int b = 0; b < NB; b++) s += g_mean[b * NL + t];
        gv[t] = s;
    }
    __syncthreads();
    for (int it = 0; it < NTOPK; it++) {
        float bv = -INFINITY; int bi = 0x7fffffff;
        for (int t = tid; t < NL; t += 512) {
            float v = gv[t];
            if (v > bv || (v == bv && t < bi)) { bv = v; bi = t; }
        }
        rv[tid] = bv; ri[tid] = bi;
        __syncthreads();
        for (int s = 256; s > 0; s >>= 1) {
            if (tid < s) {
                if (rv[tid+s] > rv[tid] || (rv[tid+s] == rv[tid] && ri[tid+s] < ri[tid])) {
                    rv[tid] = rv[tid+s]; ri[tid] = ri[tid+s];
                }
            }
            __syncthreads();
        }
        if (tid == 0) { sidx[it] = ri[0]; gv[ri[0]] = -INFINITY; }
        __syncthreads();
    }
    if (tid < NTOPK) g_idx[tid] = sidx[tid];
    if (tid < NB) {
        float vals[NTOPK];
        float mx = -INFINITY;
        for (int i = 0; i < NTOPK; i++) {
            vals[i] = g_mean[tid * NL + sidx[i]];
            mx = fmaxf(mx, vals[i]);
        }
        float s = 0.f;
        for (int i = 0; i < NTOPK; i++) { vals[i] = expf(vals[i] - mx); s += vals[i]; }
        float inv = 1.f / s;
        for (int i = 0; i < NTOPK; i++) g_wt[tid * NTOPK + i] = vals[i] * inv;
    }
}

// time-delay aggregation + residual: Of = R + sum_i w_i * V'(t+delta_i)
__global__ void roll_kernel(const __half* __restrict__ V16, const float* __restrict__ R,
                            float* __restrict__ Of, __half* __restrict__ O16)
{
    int e = blockIdx.x * blockDim.x + threadIdx.x;
    if (e >= NBLD/2) return;
    int dh = e & 255;
    int row = e >> 8;
    int b = row / NL;
    int t = row - b * NL;
    float2 r2 = *reinterpret_cast<const float2*>(R + (size_t)row * ND + dh*2);
    float sx = r2.x, sy = r2.y;
    #pragma unroll
    for (int i = 0; i < NTOPK; i++) {
        int tt = t + g_idx[i];
        if (tt >= NL) tt -= NL;
        __half2 v = *reinterpret_cast<const __half2*>(V16 + ((size_t)(b*NL + tt))*ND + dh*2);
        float2 vf = __half22float2(v);
        float w = g_wt[b * NTOPK + i];
        sx += w * vf.x; sy += w * vf.y;
    }
    *reinterpret_cast<float2*>(Of + (size_t)row * ND + dh*2) = make_float2(sx, sy);
    if (O16)
        *reinterpret_cast<__half2*>(O16 + (size_t)row * ND + dh*2) = __floats2half2_rn(sx, sy);
}

__global__ void decomp_kernel(const float* __restrict__ X, float* __restrict__ Of,
                              __half* O16)
{
    int i = blockIdx.x * blockDim.x + threadIdx.x;
    if (i >= NBLD/8) return;
    int d = i & 511;
    int c = i >> 9;
    int b = c / (NL/8);
    int tb = (c - b * (NL/8)) * 8;
    const float* Xb = X + (size_t)b * NL * ND + d;

    float acc = 0.f;
    #pragma unroll
    for (int u = -12; u <= 12; u++){
        int t = tb + u;
        t = t < 0 ? 0 : (t >= NL ? NL - 1 : t);
        acc += Xb[(size_t)t * ND];
    }
    #pragma unroll
    for (int j = 0; j < 8; j++){
        int t = tb + j;
        float x = Xb[(size_t)t * ND];
        float v = x - acc * (1.f / 25.f);
        size_t e = ((size_t)b * NL + t) * ND + d;
        if (Of)  Of[e]  = v;
        if (O16) O16[e] = __float2half_rn(v);
        int ta = t + 13; ta = ta >= NL ? NL - 1 : ta;
        int ts = t - 12; ts = ts < 0 ? 0 : ts;
        acc += Xb[(size_t)ta * ND] - Xb[(size_t)ts * ND];
    }
}

// ------------------------------- host side -----------------------------------
#define GETSYM(var, sym) do{ cudaGetSymbolAddress((void**)&var, sym); }while(0)

extern "C" void kernel_launch(void* const* d_in, const int* in_sizes, int n_in,
                              void* d_out, int out_size)
{
    const float* x_s      = (const float*)d_in[0];
    const float* x_w      = (const float*)d_in[1];
    const float* wc1_W    = (const float*)d_in[2];
    const float* wc1_b    = (const float*)d_in[3];
    const float* wc2_W    = (const float*)d_in[4];
    const float* wc2_b    = (const float*)d_in[5];
    const float* attn_W   = (const float*)d_in[6];
    const float* attn_b   = (const float*)d_in[7];
    const float* wc1_proj = (const float*)d_in[8];
    const float* wc2_proj = (const float*)d_in[9];
    const float* conv1_W  = (const float*)d_in[10];
    const float* conv2_W  = (const float*)d_in[11];
    float* out  = (float*)d_out;
    float* out2 = out + NBLD;

    float *pxs, *pxs2, *ptmp, *pv32, *pmean, *pb1024;
    GETSYM(pxs, g_xs); GETSYM(pxs2, g_xs2); GETSYM(ptmp, g_tmp);
    GETSYM(pv32, g_v32); GETSYM(pmean, g_mean); GETSYM(pb1024, g_b1024);
    __half *wf, *pweh, *pwmv, *pwtt;
    GETSYM(wf, g_wf); GETSYM(pweh, g_weh); GETSYM(pwmv, g_wmv); GETSYM(pwtt, g_wtt);
    __half *pfXW,*pfXSI,*pfK,*pfV,*pfXSa,*pfXS2,*pfXW1,*pfXSB,*pfH;
    GETSYM(pfXW, fXW);   GETSYM(pfXSI, fXSI);
    GETSYM(pfK, fK);     GETSYM(pfV, fV);
    GETSYM(pfXSa, fXSa); GETSYM(pfXS2, fXS2);
    GETSYM(pfXW1, fXW1); GETSYM(pfXSB, fXSB); GETSYM(pfH, fH);

    cudaFuncSetAttribute(gemm_s,    cudaFuncAttributeMaxDynamicSharedMemorySize, 2*SSTG);
    cudaFuncSetAttribute(gemm_w,    cudaFuncAttributeMaxDynamicSharedMemorySize, 2*SSTG);
    cudaFuncSetAttribute(embed_f16, cudaFuncAttributeMaxDynamicSharedMemorySize, 2*SSTG);
    cudaFuncSetAttribute(corr_f16,  cudaFuncAttributeMaxDynamicSharedMemorySize, 2*SSTG);

    const int nRB = (NBLD/2 + 255) / 256;
    const int nDB = (NBLD/8 + 255) / 256;
    dim3 corrG(12, 12, NB);
    dim3 embG(4, 192);

    auto G = [&](const __half* A, int woff, const float* bias, const float* R,
                 float* Cf, __half* C16, int N, int K, int relu){
        dim3 g(N >> 7, MTOT >> 7);
        gemm_s<<<g, 256, 2*SSTG>>>(A, wf + (size_t)woff * DDW, bias, R,
                                   Cf, C16, nullptr, nullptr, N, K, relu);
    };
    auto Gm = [&](const __half* A, int stage){
        dim3 g(8, MTOT >> 7);
        gemm_s<<<g, 256, 2*SSTG>>>(A, pwmv + (size_t)stage * 2 * DDW,
                                   pb1024 + stage * 1024, nullptr,
                                   nullptr, pfK, pfV, pfV, 1024, ND, 0);
    };

    // ---- weight + input conversions (batched) -------------------------------
    {
        dim3 cg(1024, 1, 5);
        cvt_f16s_b<<<cg, 256>>>(wc1_W, attn_W, wc2_W, conv1_W, conv2_W,
                                wf, wf + 4*(size_t)DDW, wf + 8*(size_t)DDW,
                                wf + 12*(size_t)DDW, wf + 16*(size_t)DDW, DDW);
        dim3 pg((DDW+255)/256, 1, 6);
        cvt_proj_f16<<<pg, 256>>>(wc1_proj, wc2_proj, pweh);
        dim3 ig((NBLD/4+255)/256, 1, 2);
        cvt_f16s_b<<<ig, 256>>>(x_w, x_s, nullptr, nullptr, nullptr,
                                pfXW, pfXSI, nullptr, nullptr, nullptr, NBLD/4);
    }

    // ---- folded weight products (batched prologue) --------------------------
    {
        dim3 trG(16, 16, 9), trB(32, 8);
        transpose_w9<<<trG, trB>>>(wc1_W, attn_W, wc2_W, pwtt);
        dim3 wg(4, 4, 6);
        gemm_w<<<wg, 256, 2*SSTG>>>(pwtt, wf, pwmv);
        dim3 mbG(16, 3);
        mkbias3<<<mbG, 256>>>(wc1_W, attn_W, wc2_W, wc1_b, attn_b, wc2_b, pb1024);
    }

    // ---- stage A: x_s += attn(q=x_w, k=v=x_s, wc1) --------------------------
    Gm(pfXSI, 0);
    cudaMemsetAsync(pmean, 0, NB*NL*sizeof(float), 0);
    corr_f16<<<corrG, 256, 2*SSTG>>>(pfXW, pfK);
    topk_kernel<<<1, 512>>>();
    roll_kernel<<<nRB, 256>>>(pfV, x_s, pxs, pfXSa);

    // ---- stage B: xw1 = token_embed(x_w, wc1_proj) --------------------------
    embed_f16<<<embG, 256, 2*SSTG>>>(pfXW, pweh, nullptr, pfXW1);

    // ---- stage C: xs += attn(xs, xs, xs, attn_W) ----------------------------
    Gm(pfXSa, 1);
    cudaMemsetAsync(pmean, 0, NB*NL*sizeof(float), 0);
    corr_f16<<<corrG, 256, 2*SSTG>>>(pfXSa, pfK);
    topk_kernel<<<1, 512>>>();
    roll_kernel<<<nRB, 256>>>(pfV, pxs, pxs, nullptr);

    // ---- stage D: xs2 = series_decomp(xs) -----------------------------------
    decomp_kernel<<<nDB, 256>>>(pxs, pxs2, pfXS2);

    // ---- stage E: xs2' = xs2 + attn(q=xw1, k=v=xs2, wc2) --------------------
    Gm(pfXS2, 2);
    cudaMemsetAsync(pmean, 0, NB*NL*sizeof(float), 0);
    corr_f16<<<corrG, 256, 2*SSTG>>>(pfXW1, pfK);
    topk_kernel<<<1, 512>>>();
    roll_kernel<<<nRB, 256>>>(pfV, pxs2, ptmp, pfXSB);

    // ---- stage F: x_w_new = token_embed(xw1, wc2_proj) -> out2 --------------
    embed_f16<<<embG, 256, 2*SSTG>>>(pfXW1, pweh + 3*(size_t)DDW, out2, nullptr);

    // ---- stage G: FFN + final series_decomp -> out --------------------------
    G(pfXSB, 12, nullptr, nullptr, nullptr, pfH, NDFF, ND,   1);
    G(pfH,   16, nullptr, ptmp,    pv32,    nullptr, ND, NDFF, 0);
    decomp_kernel<<<nDB, 256>>>(pv32, out, nullptr);
}

// round 16
// speedup vs baseline: 1.3287x; 1.0320x over previous
#include <cuda_runtime.h>
#include <cuda_fp16.h>
#include <cstdint>
#include <math.h>

#define NB    16
#define NL    1536
#define ND    512
#define NDFF  2048
#define NTOPK 7
#define NBLD  (NB*NL*ND)
#define NH    (NB*NL*NDFF)
#define DDW   262144            // 512*512
#define MTOT  (NB*NL)           // 24576

// ------------------------------- scratch ------------------------------------
__device__ float g_xs[NBLD];
__device__ float g_xs2[NBLD];
__device__ float g_tmp[NBLD];
__device__ float g_v32[NBLD];
__device__ float g_mean[NB*NL];
__device__ int   g_idx[NTOPK];
__device__ float g_wt[NB*NTOPK];
__device__ float g_b1024[3*1024];   // merged-GEMM bias per stage: [0]*512 ++ bfull

// fp16 arenas
__device__ __half g_wf[20*DDW];   // wc1(4) attn(4) wc2(4) conv1(4) conv2(4)
__device__ __half g_weh[6*DDW];   // embed weights (wc1_proj 0-2, wc2_proj 3-5)
__device__ __half g_wmv[6*DDW];   // per stage: [M ; Wvo]
__device__ __half g_wtt[9*DDW];   // transposed Wq/Wk/Wv per stage
__device__ __half fXW[NBLD];
__device__ __half fXSI[NBLD];
__device__ __half fK[NBLD], fV[NBLD];
__device__ __half fXSa[NBLD], fXS2[NBLD];
__device__ __half fXW1[NBLD];
__device__ __half fXSB[NBLD];
__device__ __half fH[NH];

// ------------------------------- helpers -------------------------------------
__device__ __forceinline__ uint32_t smem_u32(const void* p){
    uint32_t a;
    asm("{ .reg .u64 t; cvta.to.shared.u64 t, %1; cvt.u32.u64 %0, t; }":"=r"(a):"l"(p));
    return a;
}
__device__ __forceinline__ void cp16(uint32_t s, const void* g){
    asm volatile("cp.async.cg.shared.global [%0], [%1], 16;"::"r"(s),"l"(g));
}
__device__ __forceinline__ void cp_commit(){
    asm volatile("cp.async.commit_group;":::"memory");
}
__device__ __forceinline__ void ldm4(uint32_t* r, uint32_t a){
    asm volatile("ldmatrix.sync.aligned.m8n8.x4.shared.b16 {%0,%1,%2,%3}, [%4];"
        : "=r"(r[0]),"=r"(r[1]),"=r"(r[2]),"=r"(r[3]) : "r"(a));
}
__device__ __forceinline__ void mma16816f(float* c, const uint32_t* a, uint32_t b0, uint32_t b1){
    asm volatile("mma.sync.aligned.m16n8k16.row.col.f32.f16.f16.f32 "
        "{%0,%1,%2,%3},{%4,%5,%6,%7},{%8,%9},{%0,%1,%2,%3};"
        : "+f"(c[0]),"+f"(c[1]),"+f"(c[2]),"+f"(c[3])
        : "r"(a[0]),"r"(a[1]),"r"(a[2]),"r"(a[3]), "r"(b0),"r"(b1));
}
// fp16-accumulator variant (same pipe rate on sm_103; kept for lower reg use)
__device__ __forceinline__ void mma16816h(uint32_t* c, const uint32_t* a, uint32_t b0, uint32_t b1){
    asm volatile("mma.sync.aligned.m16n8k16.row.col.f16.f16.f16.f16 "
        "{%0,%1},{%2,%3,%4,%5},{%6,%7},{%0,%1};"
        : "+r"(c[0]),"+r"(c[1])
        : "r"(a[0]),"r"(a[1]),"r"(a[2]),"r"(a[3]), "r"(b0),"r"(b1));
}
#define SWZ(o) ((o) ^ (((o) >> 3) & 0x70))
#define SSTG 32768u

#define WARP_SETUP() \
    int wm = wid >> 2, wn = wid & 3; \
    int rowA = (wm << 6) + (lane & 15); \
    int rowB = (wn << 5) + (lane & 15); \
    uint32_t sA = rowA & 7, sB = rowB & 7, cq = lane >> 4; \
    uint32_t aB[4], bB[2]; \
    _Pragma("unroll") for (int mi = 0; mi < 4; mi++) aB[mi] = (uint32_t)(rowA + (mi<<4)) * 128; \
    _Pragma("unroll") for (int nj = 0; nj < 2; nj++) bB[nj] = (uint32_t)(rowB + (nj<<4)) * 128;

#define ACC_F32() \
    float acc[4][4][4]; \
    _Pragma("unroll") for (int mi = 0; mi < 4; mi++) \
        _Pragma("unroll") for (int ni = 0; ni < 4; ni++) \
            _Pragma("unroll") for (int e2 = 0; e2 < 4; e2++) acc[mi][ni][e2] = 0.f;

#define MMA_CHUNK_1T(stgbase) do{ \
    _Pragma("unroll") \
    for (int ks = 0; ks < 4; ks++){ \
        uint32_t ah[4][4], bh[2][4]; \
        uint32_t ca = ((((ks<<1)|cq) ^ sA) << 4); \
        uint32_t cb = ((((ks<<1)|cq) ^ sB) << 4); \
        _Pragma("unroll") \
        for (int mi = 0; mi < 4; mi++) ldm4(ah[mi], (stgbase) + aB[mi] + ca); \
        _Pragma("unroll") \
        for (int nj = 0; nj < 2; nj++) ldm4(bh[nj], (stgbase) + bB[nj] + cb + 16384); \
        _Pragma("unroll") \
        for (int mi = 0; mi < 4; mi++) \
            _Pragma("unroll") \
            for (int ni = 0; ni < 4; ni++){ \
                uint32_t g = ni >> 1, s = ni & 1; \
                mma16816f(acc[mi][ni], ah[mi], bh[g][s], bh[g][s+2]); \
            } \
    } \
}while(0)

#define MMA_CHUNK_H(stgbase) do{ \
    _Pragma("unroll") \
    for (int ks = 0; ks < 4; ks++){ \
        uint32_t ah[4][4], bh[2][4]; \
        uint32_t ca = ((((ks<<1)|cq) ^ sA) << 4); \
        uint32_t cb = ((((ks<<1)|cq) ^ sB) << 4); \
        _Pragma("unroll") \
        for (int mi = 0; mi < 4; mi++) ldm4(ah[mi], (stgbase) + aB[mi] + ca); \
        _Pragma("unroll") \
        for (int nj = 0; nj < 2; nj++) ldm4(bh[nj], (stgbase) + bB[nj] + cb + 16384); \
        _Pragma("unroll") \
        for (int mi = 0; mi < 4; mi++) \
            _Pragma("unroll") \
            for (int ni = 0; ni < 4; ni++){ \
                uint32_t g = ni >> 1, s = ni & 1; \
                mma16816h(hacc[mi][ni], ah[mi], bh[g][s], bh[g][s+2]); \
            } \
    } \
}while(0)

// K-loop: double-buffered cp.async pipeline over K chunks of 64
#define PIPELINE_K(NCH, ALOAD, BLOAD, CHUNK) \
    { \
        _Pragma("unroll") \
        for (int i = 0; i < 4; i++){ ALOAD(sb, i, 0); BLOAD(sb, i, 0); } \
        cp_commit(); \
    } \
    for (int c = 0; c < (NCH); c++){ \
        if (c + 1 < (NCH)){ \
            uint32_t sp_ = sb + ((c+1)&1)*SSTG; \
            size_t k0 = (size_t)(c+1) << 6; \
            _Pragma("unroll") \
            for (int i = 0; i < 4; i++){ ALOAD(sp_, i, k0); BLOAD(sp_, i, k0); } \
            cp_commit(); \
            asm volatile("cp.async.wait_group 1;":::"memory"); \
        } else { \
            asm volatile("cp.async.wait_group 0;":::"memory"); \
        } \
        __syncthreads(); \
        CHUNK(sb + (c & 1)*SSTG); \
        __syncthreads(); \
    }

// ------------------------------- single-term fp16 GEMM -----------------------
__global__ void __launch_bounds__(256,2)
gemm_s(const __half* __restrict__ A, const __half* __restrict__ W,
       const float* __restrict__ bias, const float* __restrict__ R,
       float* Cf, __half* C16, __half* C16b, __half* C16c,
       int N, int K, int relu)
{
    extern __shared__ char smem[];
    uint32_t sb = smem_u32(smem);
    int tid = threadIdx.x, wid = tid >> 5, lane = tid & 31;
    int m0 = blockIdx.y << 7, n0 = blockIdx.x << 7;

    size_t aoff[4], boff[4];
    uint32_t soff[4];
    #pragma unroll
    for (int i = 0; i < 4; i++){
        int idx = tid + (i << 8);
        int r = idx >> 3, u = idx & 7;
        aoff[i] = (size_t)(m0 + r) * K + u * 8;
        boff[i] = (size_t)(n0 + r) * K + u * 8;
        soff[i] = SWZ((uint32_t)(r * 128 + u * 16));
    }
    WARP_SETUP();
    ACC_F32();

    #define AL_(sp,i,k0) cp16((sp) + soff[i],         A + aoff[i] + (k0))
    #define BL_(sp,i,k0) cp16((sp) + 16384 + soff[i], W + boff[i] + (k0))
    int nch = K >> 6;
    PIPELINE_K(nch, AL_, BL_, MMA_CHUNK_1T);
    #undef AL_
    #undef BL_

    int gm = m0 + (wm << 6) + (lane >> 2);
    int gn = n0 + (wn << 5) + ((lane & 3) << 1);
    #pragma unroll
    for (int mi = 0; mi < 4; mi++)
        #pragma unroll
        for (int ni = 0; ni < 4; ni++)
            #pragma unroll
            for (int hh = 0; hh < 2; hh++){
                int rr = gm + (mi << 4) + hh * 8;
                int cc = gn + (ni << 3);
                float v0 = acc[mi][ni][hh*2+0];
                float v1 = acc[mi][ni][hh*2+1];
                if (bias){ v0 += bias[cc]; v1 += bias[cc+1]; }
                if (C16b){
                    int j = cc >> 9, c2 = cc & 511;
                    __half* dst = (j == 0) ? C16 : ((j == 1) ? C16b : C16c);
                    *reinterpret_cast<__half2*>(dst + (size_t)rr * 512 + c2) =
                        __floats2half2_rn(v0, v1);
                } else {
                    size_t o = (size_t)rr * N + cc;
                    if (R){ float2 r2 = *reinterpret_cast<const float2*>(R + o); v0 += r2.x; v1 += r2.y; }
                    if (relu){ v0 = fmaxf(v0, 0.f); v1 = fmaxf(v1, 0.f); }
                    if (Cf)  *reinterpret_cast<float2*>(Cf + o)  = make_float2(v0, v1);
                    if (C16) *reinterpret_cast<__half2*>(C16 + o) = __floats2half2_rn(v0, v1);
                }
            }
}

// ------------------- batched 512x512x512 weight-product GEMM -----------------
__global__ void __launch_bounds__(256,2)
gemm_w(const __half* __restrict__ wtt, const __half* __restrict__ wfp,
       __half* __restrict__ wmv)
{
    extern __shared__ char smem[];
    uint32_t sb = smem_u32(smem);
    int tid = threadIdx.x, wid = tid >> 5, lane = tid & 31;
    int z = blockIdx.z, stage = z >> 1, kind = z & 1;
    const __half* A = kind ? wfp + (size_t)(stage*4+3)*DDW : wtt + (size_t)(stage*3+0)*DDW;
    const __half* W = kind ? wtt + (size_t)(stage*3+2)*DDW : wtt + (size_t)(stage*3+1)*DDW;
    __half* C = wmv + (size_t)(stage*2+kind)*DDW;
    int m0 = blockIdx.y << 7, n0 = blockIdx.x << 7;

    size_t aoff[4], boff[4];
    uint32_t soff[4];
    #pragma unroll
    for (int i = 0; i < 4; i++){
        int idx = tid + (i << 8);
        int r = idx >> 3, u = idx & 7;
        aoff[i] = (size_t)(m0 + r) * 512 + u * 8;
        boff[i] = (size_t)(n0 + r) * 512 + u * 8;
        soff[i] = SWZ((uint32_t)(r * 128 + u * 16));
    }
    WARP_SETUP();
    ACC_F32();

    #define AL_(sp,i,k0) cp16((sp) + soff[i],         A + aoff[i] + (k0))
    #define BL_(sp,i,k0) cp16((sp) + 16384 + soff[i], W + boff[i] + (k0))
    PIPELINE_K(8, AL_, BL_, MMA_CHUNK_1T);
    #undef AL_
    #undef BL_

    int gm = m0 + (wm << 6) + (lane >> 2);
    int gn = n0 + (wn << 5) + ((lane & 3) << 1);
    #pragma unroll
    for (int mi = 0; mi < 4; mi++)
        #pragma unroll
        for (int ni = 0; ni < 4; ni++)
            #pragma unroll
            for (int hh = 0; hh < 2; hh++){
                int rr = gm + (mi << 4) + hh * 8;
                int cc = gn + (ni << 3);
                *reinterpret_cast<__half2*>(C + (size_t)rr * 512 + cc) =
                    __floats2half2_rn(acc[mi][ni][hh*2+0], acc[mi][ni][hh*2+1]);
            }
}

// --------------------------- fused token-embed (single-term) -----------------
__global__ void __launch_bounds__(256,2)
embed_f16(const __half* __restrict__ A, const __half* __restrict__ B,
          float* Cf, __half* Ch)
{
    extern __shared__ char smem[];
    uint32_t sb = smem_u32(smem);
    int tid = threadIdx.x, wid = tid >> 5, lane = tid & 31;
    int m0 = blockIdx.y << 7, n0 = blockIdx.x << 7;

    size_t aoff0[4], boff[4];
    int dm1[4], dp1[4];
    uint32_t soff[4];
    #pragma unroll
    for (int i = 0; i < 4; i++){
        int idx = tid + (i << 8);
        int r = idx >> 3, u = idx & 7;
        int am = m0 + r;
        int b = am / NL;
        int t = am - b * NL;
        aoff0[i] = (size_t)am * ND + u * 8;
        dm1[i] = ((t == 0    ? NL - 1 : t - 1) - t) * ND;
        dp1[i] = ((t == NL-1 ? 0      : t + 1) - t) * ND;
        boff[i] = (size_t)(n0 + r) * ND + u * 8;
        soff[i] = SWZ((uint32_t)(r * 128 + u * 16));
    }
    WARP_SETUP();
    ACC_F32();

    #define ELOAD(stage, c_) do{ \
        int tap_ = (c_) >> 3; \
        int kb_ = ((c_) & 7) << 6; \
        size_t bo_ = (size_t)tap_ * DDW + kb_; \
        uint32_t sp_ = sb + (stage)*SSTG; \
        _Pragma("unroll") \
        for (int i_ = 0; i_ < 4; i_++){ \
            long ao_ = (long)aoff0[i_] + (tap_ == 0 ? dm1[i_] : (tap_ == 2 ? dp1[i_] : 0)) + kb_; \
            cp16(sp_ + soff[i_],          A + ao_); \
            cp16(sp_ + 16384 + soff[i_],  B + boff[i_] + bo_); \
        } \
        cp_commit(); \
    }while(0)

    ELOAD(0, 0);
    for (int c = 0; c < 24; c++){
        if (c + 1 < 24){
            ELOAD((c+1)&1, c+1);
            asm volatile("cp.async.wait_group 1;":::"memory");
        } else {
            asm volatile("cp.async.wait_group 0;":::"memory");
        }
        __syncthreads();
        MMA_CHUNK_1T(sb + (c & 1)*SSTG);
        __syncthreads();
    }
    #undef ELOAD

    int gm = m0 + (wm << 6) + (lane >> 2);
    int gn = n0 + (wn << 5) + ((lane & 3) << 1);
    #pragma unroll
    for (int mi = 0; mi < 4; mi++)
        #pragma unroll
        for (int ni = 0; ni < 4; ni++)
            #pragma unroll
            for (int hh = 0; hh < 2; hh++){
                int rr = gm + (mi << 4) + hh * 8;
                int cc = gn + (ni << 3);
                float v0 = acc[mi][ni][hh*2+0];
                float v1 = acc[mi][ni][hh*2+1];
                size_t o = (size_t)rr * ND + cc;
                if (Cf) *reinterpret_cast<float2*>(Cf + o) = make_float2(v0, v1);
                if (Ch) *reinterpret_cast<__half2*>(Ch + o) = __floats2half2_rn(v0, v1);
            }
}

// --------------------------- correlation (fp16, f16-acc) ---------------------
__global__ void __launch_bounds__(256,2)
corr_f16(const __half* __restrict__ Qf, const __half* __restrict__ Kf)
{
    extern __shared__ char smem[];
    uint32_t sb = smem_u32(smem);
    int tid = threadIdx.x, wid = tid >> 5, lane = tid & 31;
    int bb = blockIdx.z;
    size_t base = (size_t)bb * NL * ND;
    int m0 = blockIdx.y << 7, n0 = blockIdx.x << 7;

    size_t aoff[4], boff[4];
    uint32_t soff[4];
    #pragma unroll
    for (int i = 0; i < 4; i++){
        int idx = tid + (i << 8);
        int r = idx >> 3, u = idx & 7;
        aoff[i] = base + (size_t)(m0 + r) * ND + u * 8;
        boff[i] = base + (size_t)(n0 + r) * ND + u * 8;
        soff[i] = SWZ((uint32_t)(r * 128 + u * 16));
    }
    WARP_SETUP();
    uint32_t hacc[4][4][2];
    #pragma unroll
    for (int mi = 0; mi < 4; mi++)
        #pragma unroll
        for (int ni = 0; ni < 4; ni++){ hacc[mi][ni][0] = 0u; hacc[mi][ni][1] = 0u; }

    #define AL_(sp,i,k0) cp16((sp) + soff[i],         Qf + aoff[i] + (k0))
    #define BL_(sp,i,k0) cp16((sp) + 16384 + soff[i], Kf + boff[i] + (k0))
    PIPELINE_K(8, AL_, BL_, MMA_CHUNK_H);
    #undef AL_
    #undef BL_

    float* bins = reinterpret_cast<float*>(smem);
    if (tid < 255) bins[tid] = 0.f;
    __syncthreads();

    int lm = (wm << 6) + (lane >> 2);
    int ln = (wn << 5) + ((lane & 3) << 1);
    #pragma unroll
    for (int mi = 0; mi < 4; mi++)
        #pragma unroll
        for (int ni = 0; ni < 4; ni++)
            #pragma unroll
            for (int hh = 0; hh < 2; hh++){
                int rr = lm + (mi << 4) + hh * 8;
                int cc = ln + (ni << 3);
                float2 vf = __half22float2(*reinterpret_cast<__half2*>(&hacc[mi][ni][hh]));
                atomicAdd(&bins[rr - cc + 127],     vf.x);
                atomicAdd(&bins[rr - cc - 1 + 127], vf.y);
            }
    __syncthreads();
    if (tid < 255){
        int tau = m0 - n0 + tid - 127;
        tau %= NL; if (tau < 0) tau += NL;
        atomicAdd(&g_mean[bb * NL + tau], bins[tid] * (1.f / 512.f));
    }
}

// ------------------------------ small kernels --------------------------------
__global__ void cvt_f16s_b(const float* s0, const float* s1, const float* s2,
                           const float* s3, const float* s4,
                           __half* d0, __half* d1, __half* d2, __half* d3, __half* d4,
                           int n4)
{
    int z = blockIdx.z;
    const float* x = (z==0?s0:(z==1?s1:(z==2?s2:(z==3?s3:s4))));
    __half* o      = (z==0?d0:(z==1?d1:(z==2?d2:(z==3?d3:d4))));
    int i = blockIdx.x * blockDim.x + threadIdx.x;
    if (i >= n4) return;
    float4 v = reinterpret_cast<const float4*>(x)[i];
    __half2* op = reinterpret_cast<__half2*>(o);
    op[2*i]   = __floats2half2_rn(v.x, v.y);
    op[2*i+1] = __floats2half2_rn(v.z, v.w);
}

__global__ void cvt_proj_f16(const float* __restrict__ src1, const float* __restrict__ src2,
                             __half* __restrict__ h)
{
    int z = blockIdx.z;                 // 0..5
    const float* src = (z < 3 ? src1 + (z % 3) : src2 + (z % 3));
    __half* d = h + (size_t)z * DDW;
    int e = blockIdx.x * blockDim.x + threadIdx.x;
    if (e >= DDW) return;
    int n = e >> 9, k = e & 511;
    d[e] = __float2half_rn(src[n * 1536 + k * 3]);
}

__global__ void transpose_w9(const float* __restrict__ w1, const float* __restrict__ w2,
                             const float* __restrict__ w3, __half* __restrict__ dst)
{
    __shared__ float tile[32][33];
    int z = blockIdx.z;
    int stage = z / 3, which = z - stage * 3;
    const float* src = (stage == 0 ? w1 : (stage == 1 ? w2 : w3)) + (size_t)which * DDW;
    __half* d = dst + (size_t)z * DDW;
    int bx = blockIdx.x << 5, by = blockIdx.y << 5;
    int tx = threadIdx.x, ty = threadIdx.y;   // (32, 8)
    #pragma unroll
    for (int j = 0; j < 32; j += 8)
        tile[ty + j][tx] = src[(size_t)(by + ty + j) * 512 + bx + tx];
    __syncthreads();
    #pragma unroll
    for (int j = 0; j < 32; j += 8)
        d[(size_t)(bx + ty + j) * 512 + by + tx] = __float2half_rn(tile[tx][ty + j]);
}

__global__ void mkbias3(const float* __restrict__ w1, const float* __restrict__ w2,
                        const float* __restrict__ w3,
                        const float* __restrict__ b1, const float* __restrict__ b2,
                        const float* __restrict__ b3,
                        float* __restrict__ b1024)
{
    int s = blockIdx.y;
    const float* Wsel = (s == 0 ? w1 : (s == 1 ? w2 : w3));
    const float* bsel = (s == 0 ? b1 : (s == 1 ? b2 : b3));
    const float* Wo = Wsel + 3*DDW;
    const float* bv = bsel + 2*ND;
    const float* bo = bsel + 3*ND;
    float* bout = b1024 + s * 1024;
    int tid = threadIdx.x, wid = tid >> 5, lane = tid & 31;

    if (tid < 32) bout[blockIdx.x * 32 + tid] = 0.f;

    #pragma unroll
    for (int i = 0; i < 4; i++){
        int n = blockIdx.x * 32 + wid * 4 + i;
        const float* row = Wo + (size_t)n * 512;
        float sum = 0.f;
        #pragma unroll
        for (int j = 0; j < 16; j++)
            sum += row[lane + j * 32] * bv[lane + j * 32];
        #pragma unroll
        for (int off = 16; off > 0; off >>= 1)
            sum += __shfl_down_sync(0xffffffff, sum, off);
        if (lane == 0) bout[512 + n] = sum + bo[n];
    }
}

__global__ void topk_kernel()
{
    __shared__ float gv[NL];
    __shared__ float rv[512];
    __shared__ int   ri[512];
    __shared__ int   sidx[NTOPK];
    int tid = threadIdx.x;
    for (int t = tid; t < NL; t += 512) {
        float s = 0.f;
        for (int b = 0; b < NB; b++) s += g_mean[b * NL + t];
        gv[t] = s;
    }
    __syncthreads();
    for (int it = 0; it < NTOPK; it++) {
        float bv = -INFINITY; int bi = 0x7fffffff;
        for (int t = tid; t < NL; t += 512) {
            float v = gv[t];
            if (v > bv || (v == bv && t < bi)) { bv = v; bi = t; }
        }
        rv[tid] = bv; ri[tid] = bi;
        __syncthreads();
        for (int s = 256; s > 0; s >>= 1) {
            if (tid < s) {
                if (rv[tid+s] > rv[tid] || (rv[tid+s] == rv[tid] && ri[tid+s] < ri[tid])) {
                    rv[tid] = rv[tid+s]; ri[tid] = ri[tid+s];
                }
            }
            __syncthreads();
        }
        if (tid == 0) { sidx[it] = ri[0]; gv[ri[0]] = -INFINITY; }
        __syncthreads();
    }
    if (tid < NTOPK) g_idx[tid] = sidx[tid];
    if (tid < NB) {
        float vals[NTOPK];
        float mx = -INFINITY;
        for (int i = 0; i < NTOPK; i++) {
            vals[i] = g_mean[tid * NL + sidx[i]];
            mx = fmaxf(mx, vals[i]);
        }
        float s = 0.f;
        for (int i = 0; i < NTOPK; i++) { vals[i] = expf(vals[i] - mx); s += vals[i]; }
        float inv = 1.f / s;
        for (int i = 0; i < NTOPK; i++) g_wt[tid * NTOPK + i] = vals[i] * inv;
    }
}

__global__ void roll_kernel(const __half* __restrict__ V16, const float* __restrict__ R,
                            float* __restrict__ Of, __half* __restrict__ O16)
{
    int e = blockIdx.x * blockDim.x + threadIdx.x;
    if (e >= NBLD/2) return;
    int dh = e & 255;
    int row = e >> 8;
    int b = row / NL;
    int t = row - b * NL;
    float2 r2 = *reinterpret_cast<const float2*>(R + (size_t)row * ND + dh*2);
    float sx = r2.x, sy = r2.y;
    #pragma unroll
    for (int i = 0; i < NTOPK; i++) {
        int tt = t + g_idx[i];
        if (tt >= NL) tt -= NL;
        __half2 v = *reinterpret_cast<const __half2*>(V16 + ((size_t)(b*NL + tt))*ND + dh*2);
        float2 vf = __half22float2(v);
        float w = g_wt[b * NTOPK + i];
        sx += w * vf.x; sy += w * vf.y;
    }
    *reinterpret_cast<float2*>(Of + (size_t)row * ND + dh*2) = make_float2(sx, sy);
    if (O16)
        *reinterpret_cast<__half2*>(O16 + (size_t)row * ND + dh*2) = __floats2half2_rn(sx, sy);
}

__global__ void decomp_kernel(const float* __restrict__ X, float* __restrict__ Of,
                              __half* O16)
{
    int i = blockIdx.x * blockDim.x + threadIdx.x;
    if (i >= NBLD/8) return;
    int d = i & 511;
    int c = i >> 9;
    int b = c / (NL/8);
    int tb = (c - b * (NL/8)) * 8;
    const float* Xb = X + (size_t)b * NL * ND + d;

    float acc = 0.f;
    #pragma unroll
    for (int u = -12; u <= 12; u++){
        int t = tb + u;
        t = t < 0 ? 0 : (t >= NL ? NL - 1 : t);
        acc += Xb[(size_t)t * ND];
    }
    #pragma unroll
    for (int j = 0; j < 8; j++){
        int t = tb + j;
        float x = Xb[(size_t)t * ND];
        float v = x - acc * (1.f / 25.f);
        size_t e = ((size_t)b * NL + t) * ND + d;
        if (Of)  Of[e]  = v;
        if (O16) O16[e] = __float2half_rn(v);
        int ta = t + 13; ta = ta >= NL ? NL - 1 : ta;
        int ts = t - 12; ts = ts < 0 ? 0 : ts;
        acc += Xb[(size_t)ta * ND] - Xb[(size_t)ts * ND];
    }
}

// ------------------------------- host side -----------------------------------
#define GETSYM(var, sym) do{ cudaGetSymbolAddress((void**)&var, sym); }while(0)

extern "C" void kernel_launch(void* const* d_in, const int* in_sizes, int n_in,
                              void* d_out, int out_size)
{
    const float* x_s      = (const float*)d_in[0];
    const float* x_w      = (const float*)d_in[1];
    const float* wc1_W    = (const float*)d_in[2];
    const float* wc1_b    = (const float*)d_in[3];
    const float* wc2_W    = (const float*)d_in[4];
    const float* wc2_b    = (const float*)d_in[5];
    const float* attn_W   = (const float*)d_in[6];
    const float* attn_b   = (const float*)d_in[7];
    const float* wc1_proj = (const float*)d_in[8];
    const float* wc2_proj = (const float*)d_in[9];
    const float* conv1_W  = (const float*)d_in[10];
    const float* conv2_W  = (const float*)d_in[11];
    float* out  = (float*)d_out;
    float* out2 = out + NBLD;

    float *pxs, *pxs2, *ptmp, *pv32, *pmean, *pb1024;
    GETSYM(pxs, g_xs); GETSYM(pxs2, g_xs2); GETSYM(ptmp, g_tmp);
    GETSYM(pv32, g_v32); GETSYM(pmean, g_mean); GETSYM(pb1024, g_b1024);
    __half *wf, *pweh, *pwmv, *pwtt;
    GETSYM(wf, g_wf); GETSYM(pweh, g_weh); GETSYM(pwmv, g_wmv); GETSYM(pwtt, g_wtt);
    __half *pfXW,*pfXSI,*pfK,*pfV,*pfXSa,*pfXS2,*pfXW1,*pfXSB,*pfH;
    GETSYM(pfXW, fXW);   GETSYM(pfXSI, fXSI);
    GETSYM(pfK, fK);     GETSYM(pfV, fV);
    GETSYM(pfXSa, fXSa); GETSYM(pfXS2, fXS2);
    GETSYM(pfXW1, fXW1); GETSYM(pfXSB, fXSB); GETSYM(pfH, fH);

    cudaFuncSetAttribute(gemm_s,    cudaFuncAttributeMaxDynamicSharedMemorySize, 2*SSTG);
    cudaFuncSetAttribute(gemm_w,    cudaFuncAttributeMaxDynamicSharedMemorySize, 2*SSTG);
    cudaFuncSetAttribute(embed_f16, cudaFuncAttributeMaxDynamicSharedMemorySize, 2*SSTG);
    cudaFuncSetAttribute(corr_f16,  cudaFuncAttributeMaxDynamicSharedMemorySize, 2*SSTG);

    // second stream + events for the independent embed chain (created once;
    // host-side objects only — no device memory involved)
    static cudaStream_t s2 = nullptr;
    static cudaEvent_t evCvt = nullptr, evB = nullptr, evF = nullptr;
    if (s2 == nullptr){
        cudaStreamCreateWithFlags(&s2, cudaStreamNonBlocking);
        cudaEventCreateWithFlags(&evCvt, cudaEventDisableTiming);
        cudaEventCreateWithFlags(&evB,   cudaEventDisableTiming);
        cudaEventCreateWithFlags(&evF,   cudaEventDisableTiming);
    }

    const int nRB = (NBLD/2 + 255) / 256;
    const int nDB = (NBLD/8 + 255) / 256;
    dim3 corrG(12, 12, NB);
    dim3 embG(4, 192);

    auto G = [&](const __half* A, int woff, const float* bias, const float* R,
                 float* Cf, __half* C16, int N, int K, int relu){
        dim3 g(N >> 7, MTOT >> 7);
        gemm_s<<<g, 256, 2*SSTG>>>(A, wf + (size_t)woff * DDW, bias, R,
                                   Cf, C16, nullptr, nullptr, N, K, relu);
    };
    auto Gm = [&](const __half* A, int stage){
        dim3 g(8, MTOT >> 7);
        gemm_s<<<g, 256, 2*SSTG>>>(A, pwmv + (size_t)stage * 2 * DDW,
                                   pb1024 + stage * 1024, nullptr,
                                   nullptr, pfK, pfV, pfV, 1024, ND, 0);
    };

    // ---- weight + input conversions (batched, stream 0) ---------------------
    {
        dim3 cg(1024, 1, 5);
        cvt_f16s_b<<<cg, 256>>>(wc1_W, attn_W, wc2_W, conv1_W, conv2_W,
                                wf, wf + 4*(size_t)DDW, wf + 8*(size_t)DDW,
                                wf + 12*(size_t)DDW, wf + 16*(size_t)DDW, DDW);
        dim3 pg((DDW+255)/256, 1, 6);
        cvt_proj_f16<<<pg, 256>>>(wc1_proj, wc2_proj, pweh);
        dim3 ig((NBLD/4+255)/256, 1, 2);
        cvt_f16s_b<<<ig, 256>>>(x_w, x_s, nullptr, nullptr, nullptr,
                                pfXW, pfXSI, nullptr, nullptr, nullptr, NBLD/4);
    }

    // ---- fork: independent embed chain on s2 --------------------------------
    cudaEventRecord(evCvt, 0);
    cudaStreamWaitEvent(s2, evCvt, 0);
    // stage B: xw1 = token_embed(x_w, wc1_proj)
    embed_f16<<<embG, 256, 2*SSTG, s2>>>(pfXW, pweh, nullptr, pfXW1);
    cudaEventRecord(evB, s2);
    // stage F: x_w_new = token_embed(xw1, wc2_proj) -> out2
    embed_f16<<<embG, 256, 2*SSTG, s2>>>(pfXW1, pweh + 3*(size_t)DDW, out2, nullptr);
    cudaEventRecord(evF, s2);

    // ---- folded weight products (batched prologue, stream 0) ----------------
    {
        dim3 trG(16, 16, 9), trB(32, 8);
        transpose_w9<<<trG, trB>>>(wc1_W, attn_W, wc2_W, pwtt);
        dim3 wg(4, 4, 6);
        gemm_w<<<wg, 256, 2*SSTG>>>(pwtt, wf, pwmv);
        dim3 mbG(16, 3);
        mkbias3<<<mbG, 256>>>(wc1_W, attn_W, wc2_W, wc1_b, attn_b, wc2_b, pb1024);
    }

    // ---- stage A: x_s += attn(q=x_w, k=v=x_s, wc1) --------------------------
    Gm(pfXSI, 0);
    cudaMemsetAsync(pmean, 0, NB*NL*sizeof(float), 0);
    corr_f16<<<corrG, 256, 2*SSTG>>>(pfXW, pfK);
    topk_kernel<<<1, 512>>>();
    roll_kernel<<<nRB, 256>>>(pfV, x_s, pxs, pfXSa);

    // ---- stage C: xs += attn(xs, xs, xs, attn_W) ----------------------------
    Gm(pfXSa, 1);
    cudaMemsetAsync(pmean, 0, NB*NL*sizeof(float), 0);
    corr_f16<<<corrG, 256, 2*SSTG>>>(pfXSa, pfK);
    topk_kernel<<<1, 512>>>();
    roll_kernel<<<nRB, 256>>>(pfV, pxs, pxs, nullptr);

    // ---- stage D: xs2 = series_decomp(xs) -----------------------------------
    decomp_kernel<<<nDB, 256>>>(pxs, pxs2, pfXS2);

    // ---- stage E: xs2' = xs2 + attn(q=xw1, k=v=xs2, wc2) --------------------
    Gm(pfXS2, 2);
    cudaMemsetAsync(pmean, 0, NB*NL*sizeof(float), 0);
    cudaStreamWaitEvent(0, evB, 0);      // corr E reads pfXW1 from s2's embed B
    corr_f16<<<corrG, 256, 2*SSTG>>>(pfXW1, pfK);
    topk_kernel<<<1, 512>>>();
    roll_kernel<<<nRB, 256>>>(pfV, pxs2, ptmp, pfXSB);

    // ---- stage G: FFN + final series_decomp -> out --------------------------
    G(pfXSB, 12, nullptr, nullptr, nullptr, pfH, NDFF, ND,   1);
    G(pfH,   16, nullptr, ptmp,    pv32,    nullptr, ND, NDFF, 0);
    decomp_kernel<<<nDB, 256>>>(pv32, out, nullptr);

    // ---- join: out2 (stage F) must complete before graph end ----------------
    cudaStreamWaitEvent(0, evF, 0);
}

// round 17
// speedup vs baseline: 1.3376x; 1.0067x over previous
#include <cuda_runtime.h>
#include <cuda_fp16.h>
#include <cstdint>
#include <math.h>

#define NB    16
#define NL    1536
#define ND    512
#define NDFF  2048
#define NTOPK 7
#define NBLD  (NB*NL*ND)
#define NH    (NB*NL*NDFF)
#define DDW   262144            // 512*512
#define MTOT  (NB*NL)           // 24576

// ------------------------------- scratch ------------------------------------
__device__ float g_xs[NBLD];
__device__ float g_xs2[NBLD];
__device__ float g_tmp[NBLD];
__device__ float g_v32[NBLD];
__device__ float g_mean[NB*NL];
__device__ int   g_idx[NTOPK];
__device__ float g_wt[NB*NTOPK];
__device__ float g_b1024[3*1024];   // per stage: [0]*512 ++ (Wo·bv + bo)

// fp16 arenas
__device__ __half g_wf[20*DDW];   // wc1(4) attn(4) wc2(4) conv1(4) conv2(4)
__device__ __half g_weh[6*DDW];   // embed weights (wc1_proj 0-2, wc2_proj 3-5)
__device__ __half g_wmv[6*DDW];   // per stage: [M ; Wvo]
__device__ __half g_wtt[9*DDW];   // transposed Wq/Wk/Wv per stage
__device__ __half fXW[NBLD];
__device__ __half fXSI[NBLD];
__device__ __half fK[NBLD], fV[NBLD];
__device__ __half fXSa[NBLD], fXS2[NBLD];
__device__ __half fXW1[NBLD];
__device__ __half fXSB[NBLD];
__device__ __half fH[NH];

// ------------------------------- helpers -------------------------------------
__device__ __forceinline__ uint32_t smem_u32(const void* p){
    uint32_t a;
    asm("{ .reg .u64 t; cvta.to.shared.u64 t, %1; cvt.u32.u64 %0, t; }":"=r"(a):"l"(p));
    return a;
}
__device__ __forceinline__ void cp16(uint32_t s, const void* g){
    asm volatile("cp.async.cg.shared.global [%0], [%1], 16;"::"r"(s),"l"(g));
}
__device__ __forceinline__ void cp_commit(){
    asm volatile("cp.async.commit_group;":::"memory");
}
__device__ __forceinline__ void ldm4(uint32_t* r, uint32_t a){
    asm volatile("ldmatrix.sync.aligned.m8n8.x4.shared.b16 {%0,%1,%2,%3}, [%4];"
        : "=r"(r[0]),"=r"(r[1]),"=r"(r[2]),"=r"(r[3]) : "r"(a));
}
__device__ __forceinline__ void mma16816f(float* c, const uint32_t* a, uint32_t b0, uint32_t b1){
    asm volatile("mma.sync.aligned.m16n8k16.row.col.f32.f16.f16.f32 "
        "{%0,%1,%2,%3},{%4,%5,%6,%7},{%8,%9},{%0,%1,%2,%3};"
        : "+f"(c[0]),"+f"(c[1]),"+f"(c[2]),"+f"(c[3])
        : "r"(a[0]),"r"(a[1]),"r"(a[2]),"r"(a[3]), "r"(b0),"r"(b1));
}
__device__ __forceinline__ void mma16816h(uint32_t* c, const uint32_t* a, uint32_t b0, uint32_t b1){
    asm volatile("mma.sync.aligned.m16n8k16.row.col.f16.f16.f16.f16 "
        "{%0,%1},{%2,%3,%4,%5},{%6,%7},{%0,%1};"
        : "+r"(c[0]),"+r"(c[1])
        : "r"(a[0]),"r"(a[1]),"r"(a[2]),"r"(a[3]), "r"(b0),"r"(b1));
}
#define SWZ(o) ((o) ^ (((o) >> 3) & 0x70))
#define SSTG 32768u

#define WARP_SETUP() \
    int wm = wid >> 2, wn = wid & 3; \
    int rowA = (wm << 6) + (lane & 15); \
    int rowB = (wn << 5) + (lane & 15); \
    uint32_t sA = rowA & 7, sB = rowB & 7, cq = lane >> 4; \
    uint32_t aB[4], bB[2]; \
    _Pragma("unroll") for (int mi = 0; mi < 4; mi++) aB[mi] = (uint32_t)(rowA + (mi<<4)) * 128; \
    _Pragma("unroll") for (int nj = 0; nj < 2; nj++) bB[nj] = (uint32_t)(rowB + (nj<<4)) * 128;

#define ACC_F32() \
    float acc[4][4][4]; \
    _Pragma("unroll") for (int mi = 0; mi < 4; mi++) \
        _Pragma("unroll") for (int ni = 0; ni < 4; ni++) \
            _Pragma("unroll") for (int e2 = 0; e2 < 4; e2++) acc[mi][ni][e2] = 0.f;

#define MMA_CHUNK_1T(stgbase) do{ \
    _Pragma("unroll") \
    for (int ks = 0; ks < 4; ks++){ \
        uint32_t ah[4][4], bh[2][4]; \
        uint32_t ca = ((((ks<<1)|cq) ^ sA) << 4); \
        uint32_t cb = ((((ks<<1)|cq) ^ sB) << 4); \
        _Pragma("unroll") \
        for (int mi = 0; mi < 4; mi++) ldm4(ah[mi], (stgbase) + aB[mi] + ca); \
        _Pragma("unroll") \
        for (int nj = 0; nj < 2; nj++) ldm4(bh[nj], (stgbase) + bB[nj] + cb + 16384); \
        _Pragma("unroll") \
        for (int mi = 0; mi < 4; mi++) \
            _Pragma("unroll") \
            for (int ni = 0; ni < 4; ni++){ \
                uint32_t g = ni >> 1, s = ni & 1; \
                mma16816f(acc[mi][ni], ah[mi], bh[g][s], bh[g][s+2]); \
            } \
    } \
}while(0)

#define MMA_CHUNK_H(stgbase) do{ \
    _Pragma("unroll") \
    for (int ks = 0; ks < 4; ks++){ \
        uint32_t ah[4][4], bh[2][4]; \
        uint32_t ca = ((((ks<<1)|cq) ^ sA) << 4); \
        uint32_t cb = ((((ks<<1)|cq) ^ sB) << 4); \
        _Pragma("unroll") \
        for (int mi = 0; mi < 4; mi++) ldm4(ah[mi], (stgbase) + aB[mi] + ca); \
        _Pragma("unroll") \
        for (int nj = 0; nj < 2; nj++) ldm4(bh[nj], (stgbase) + bB[nj] + cb + 16384); \
        _Pragma("unroll") \
        for (int mi = 0; mi < 4; mi++) \
            _Pragma("unroll") \
            for (int ni = 0; ni < 4; ni++){ \
                uint32_t g = ni >> 1, s = ni & 1; \
                mma16816h(hacc[mi][ni], ah[mi], bh[g][s], bh[g][s+2]); \
            } \
    } \
}while(0)

#define PIPELINE_K(NCH, ALOAD, BLOAD, CHUNK) \
    { \
        _Pragma("unroll") \
        for (int i = 0; i < 4; i++){ ALOAD(sb, i, 0); BLOAD(sb, i, 0); } \
        cp_commit(); \
    } \
    for (int c = 0; c < (NCH); c++){ \
        if (c + 1 < (NCH)){ \
            uint32_t sp_ = sb + ((c+1)&1)*SSTG; \
            size_t k0 = (size_t)(c+1) << 6; \
            _Pragma("unroll") \
            for (int i = 0; i < 4; i++){ ALOAD(sp_, i, k0); BLOAD(sp_, i, k0); } \
            cp_commit(); \
            asm volatile("cp.async.wait_group 1;":::"memory"); \
        } else { \
            asm volatile("cp.async.wait_group 0;":::"memory"); \
        } \
        __syncthreads(); \
        CHUNK(sb + (c & 1)*SSTG); \
        __syncthreads(); \
    }

// ------------------------------- single-term fp16 GEMM -----------------------
__global__ void __launch_bounds__(256,2)
gemm_s(const __half* __restrict__ A, const __half* __restrict__ W,
       const float* __restrict__ bias, const float* __restrict__ R,
       float* Cf, __half* C16, int N, int K, int relu)
{
    extern __shared__ char smem[];
    uint32_t sb = smem_u32(smem);
    int tid = threadIdx.x, wid = tid >> 5, lane = tid & 31;
    int m0 = blockIdx.y << 7, n0 = blockIdx.x << 7;

    size_t aoff[4], boff[4];
    uint32_t soff[4];
    #pragma unroll
    for (int i = 0; i < 4; i++){
        int idx = tid + (i << 8);
        int r = idx >> 3, u = idx & 7;
        aoff[i] = (size_t)(m0 + r) * K + u * 8;
        boff[i] = (size_t)(n0 + r) * K + u * 8;
        soff[i] = SWZ((uint32_t)(r * 128 + u * 16));
    }
    WARP_SETUP();
    ACC_F32();

    #define AL_(sp,i,k0) cp16((sp) + soff[i],         A + aoff[i] + (k0))
    #define BL_(sp,i,k0) cp16((sp) + 16384 + soff[i], W + boff[i] + (k0))
    int nch = K >> 6;
    PIPELINE_K(nch, AL_, BL_, MMA_CHUNK_1T);
    #undef AL_
    #undef BL_

    int gm = m0 + (wm << 6) + (lane >> 2);
    int gn = n0 + (wn << 5) + ((lane & 3) << 1);
    #pragma unroll
    for (int mi = 0; mi < 4; mi++)
        #pragma unroll
        for (int ni = 0; ni < 4; ni++)
            #pragma unroll
            for (int hh = 0; hh < 2; hh++){
                int rr = gm + (mi << 4) + hh * 8;
                int cc = gn + (ni << 3);
                float v0 = acc[mi][ni][hh*2+0];
                float v1 = acc[mi][ni][hh*2+1];
                if (bias){ v0 += bias[cc]; v1 += bias[cc+1]; }
                size_t o = (size_t)rr * N + cc;
                if (R){ float2 r2 = *reinterpret_cast<const float2*>(R + o); v0 += r2.x; v1 += r2.y; }
                if (relu){ v0 = fmaxf(v0, 0.f); v1 = fmaxf(v1, 0.f); }
                if (Cf)  *reinterpret_cast<float2*>(Cf + o)  = make_float2(v0, v1);
                if (C16) *reinterpret_cast<__half2*>(C16 + o) = __floats2half2_rn(v0, v1);
            }
}

// ------------------- batched 512x512x512 weight-product GEMM -----------------
__global__ void __launch_bounds__(256,2)
gemm_w(const __half* __restrict__ wtt, const __half* __restrict__ wfp,
       __half* __restrict__ wmv)
{
    extern __shared__ char smem[];
    uint32_t sb = smem_u32(smem);
    int tid = threadIdx.x, wid = tid >> 5, lane = tid & 31;
    int z = blockIdx.z, stage = z >> 1, kind = z & 1;
    const __half* A = kind ? wfp + (size_t)(stage*4+3)*DDW : wtt + (size_t)(stage*3+0)*DDW;
    const __half* W = kind ? wtt + (size_t)(stage*3+2)*DDW : wtt + (size_t)(stage*3+1)*DDW;
    __half* C = wmv + (size_t)(stage*2+kind)*DDW;
    int m0 = blockIdx.y << 7, n0 = blockIdx.x << 7;

    size_t aoff[4], boff[4];
    uint32_t soff[4];
    #pragma unroll
    for (int i = 0; i < 4; i++){
        int idx = tid + (i << 8);
        int r = idx >> 3, u = idx & 7;
        aoff[i] = (size_t)(m0 + r) * 512 + u * 8;
        boff[i] = (size_t)(n0 + r) * 512 + u * 8;
        soff[i] = SWZ((uint32_t)(r * 128 + u * 16));
    }
    WARP_SETUP();
    ACC_F32();

    #define AL_(sp,i,k0) cp16((sp) + soff[i],         A + aoff[i] + (k0))
    #define BL_(sp,i,k0) cp16((sp) + 16384 + soff[i], W + boff[i] + (k0))
    PIPELINE_K(8, AL_, BL_, MMA_CHUNK_1T);
    #undef AL_
    #undef BL_

    int gm = m0 + (wm << 6) + (lane >> 2);
    int gn = n0 + (wn << 5) + ((lane & 3) << 1);
    #pragma unroll
    for (int mi = 0; mi < 4; mi++)
        #pragma unroll
        for (int ni = 0; ni < 4; ni++)
            #pragma unroll
            for (int hh = 0; hh < 2; hh++){
                int rr = gm + (mi << 4) + hh * 8;
                int cc = gn + (ni << 3);
                *reinterpret_cast<__half2*>(C + (size_t)rr * 512 + cc) =
                    __floats2half2_rn(acc[mi][ni][hh*2+0], acc[mi][ni][hh*2+1]);
            }
}

// --------------------------- fused token-embed (single-term) -----------------
__global__ void __launch_bounds__(256,2)
embed_f16(const __half* __restrict__ A, const __half* __restrict__ B,
          float* Cf, __half* Ch)
{
    extern __shared__ char smem[];
    uint32_t sb = smem_u32(smem);
    int tid = threadIdx.x, wid = tid >> 5, lane = tid & 31;
    int m0 = blockIdx.y << 7, n0 = blockIdx.x << 7;

    size_t aoff0[4], boff[4];
    int dm1[4], dp1[4];
    uint32_t soff[4];
    #pragma unroll
    for (int i = 0; i < 4; i++){
        int idx = tid + (i << 8);
        int r = idx >> 3, u = idx & 7;
        int am = m0 + r;
        int b = am / NL;
        int t = am - b * NL;
        aoff0[i] = (size_t)am * ND + u * 8;
        dm1[i] = ((t == 0    ? NL - 1 : t - 1) - t) * ND;
        dp1[i] = ((t == NL-1 ? 0      : t + 1) - t) * ND;
        boff[i] = (size_t)(n0 + r) * ND + u * 8;
        soff[i] = SWZ((uint32_t)(r * 128 + u * 16));
    }
    WARP_SETUP();
    ACC_F32();

    #define ELOAD(stage, c_) do{ \
        int tap_ = (c_) >> 3; \
        int kb_ = ((c_) & 7) << 6; \
        size_t bo_ = (size_t)tap_ * DDW + kb_; \
        uint32_t sp_ = sb + (stage)*SSTG; \
        _Pragma("unroll") \
        for (int i_ = 0; i_ < 4; i_++){ \
            long ao_ = (long)aoff0[i_] + (tap_ == 0 ? dm1[i_] : (tap_ == 2 ? dp1[i_] : 0)) + kb_; \
            cp16(sp_ + soff[i_],          A + ao_); \
            cp16(sp_ + 16384 + soff[i_],  B + boff[i_] + bo_); \
        } \
        cp_commit(); \
    }while(0)

    ELOAD(0, 0);
    for (int c = 0; c < 24; c++){
        if (c + 1 < 24){
            ELOAD((c+1)&1, c+1);
            asm volatile("cp.async.wait_group 1;":::"memory");
        } else {
            asm volatile("cp.async.wait_group 0;":::"memory");
        }
        __syncthreads();
        MMA_CHUNK_1T(sb + (c & 1)*SSTG);
        __syncthreads();
    }
    #undef ELOAD

    int gm = m0 + (wm << 6) + (lane >> 2);
    int gn = n0 + (wn << 5) + ((lane & 3) << 1);
    #pragma unroll
    for (int mi = 0; mi < 4; mi++)
        #pragma unroll
        for (int ni = 0; ni < 4; ni++)
            #pragma unroll
            for (int hh = 0; hh < 2; hh++){
                int rr = gm + (mi << 4) + hh * 8;
                int cc = gn + (ni << 3);
                float v0 = acc[mi][ni][hh*2+0];
                float v1 = acc[mi][ni][hh*2+1];
                size_t o = (size_t)rr * ND + cc;
                if (Cf) *reinterpret_cast<float2*>(Cf + o) = make_float2(v0, v1);
                if (Ch) *reinterpret_cast<__half2*>(Ch + o) = __floats2half2_rn(v0, v1);
            }
}

// --------------------------- correlation (fp16, f16-acc) ---------------------
__global__ void __launch_bounds__(256,2)
corr_f16(const __half* __restrict__ Qf, const __half* __restrict__ Kf)
{
    extern __shared__ char smem[];
    uint32_t sb = smem_u32(smem);
    int tid = threadIdx.x, wid = tid >> 5, lane = tid & 31;
    int bb = blockIdx.z;
    size_t base = (size_t)bb * NL * ND;
    int m0 = blockIdx.y << 7, n0 = blockIdx.x << 7;

    size_t aoff[4], boff[4];
    uint32_t soff[4];
    #pragma unroll
    for (int i = 0; i < 4; i++){
        int idx = tid + (i << 8);
        int r = idx >> 3, u = idx & 7;
        aoff[i] = base + (size_t)(m0 + r) * ND + u * 8;
        boff[i] = base + (size_t)(n0 + r) * ND + u * 8;
        soff[i] = SWZ((uint32_t)(r * 128 + u * 16));
    }
    WARP_SETUP();
    uint32_t hacc[4][4][2];
    #pragma unroll
    for (int mi = 0; mi < 4; mi++)
        #pragma unroll
        for (int ni = 0; ni < 4; ni++){ hacc[mi][ni][0] = 0u; hacc[mi][ni][1] = 0u; }

    #define AL_(sp,i,k0) cp16((sp) + soff[i],         Qf + aoff[i] + (k0))
    #define BL_(sp,i,k0) cp16((sp) + 16384 + soff[i], Kf + boff[i] + (k0))
    PIPELINE_K(8, AL_, BL_, MMA_CHUNK_H);
    #undef AL_
    #undef BL_

    float* bins = reinterpret_cast<float*>(smem);
    if (tid < 255) bins[tid] = 0.f;
    __syncthreads();

    int lm = (wm << 6) + (lane >> 2);
    int ln = (wn << 5) + ((lane & 3) << 1);
    #pragma unroll
    for (int mi = 0; mi < 4; mi++)
        #pragma unroll
        for (int ni = 0; ni < 4; ni++)
            #pragma unroll
            for (int hh = 0; hh < 2; hh++){
                int rr = lm + (mi << 4) + hh * 8;
                int cc = ln + (ni << 3);
                float2 vf = __half22float2(*reinterpret_cast<__half2*>(&hacc[mi][ni][hh]));
                atomicAdd(&bins[rr - cc + 127],     vf.x);
                atomicAdd(&bins[rr - cc - 1 + 127], vf.y);
            }
    __syncthreads();
    if (tid < 255){
        int tau = m0 - n0 + tid - 127;
        tau %= NL; if (tau < 0) tau += NL;
        atomicAdd(&g_mean[bb * NL + tau], bins[tid] * (1.f / 512.f));
    }
}

// ------------------------------ small kernels --------------------------------
__global__ void cvt_f16s_b(const float* s0, const float* s1, const float* s2,
                           const float* s3, const float* s4,
                           __half* d0, __half* d1, __half* d2, __half* d3, __half* d4,
                           int n4)
{
    int z = blockIdx.z;
    const float* x = (z==0?s0:(z==1?s1:(z==2?s2:(z==3?s3:s4))));
    __half* o      = (z==0?d0:(z==1?d1:(z==2?d2:(z==3?d3:d4))));
    int i = blockIdx.x * blockDim.x + threadIdx.x;
    if (i >= n4) return;
    float4 v = reinterpret_cast<const float4*>(x)[i];
    __half2* op = reinterpret_cast<__half2*>(o);
    op[2*i]   = __floats2half2_rn(v.x, v.y);
    op[2*i+1] = __floats2half2_rn(v.z, v.w);
}

__global__ void cvt_proj_f16(const float* __restrict__ src1, const float* __restrict__ src2,
                             __half* __restrict__ h)
{
    int z = blockIdx.z;                 // 0..5
    const float* src = (z < 3 ? src1 + (z % 3) : src2 + (z % 3));
    __half* d = h + (size_t)z * DDW;
    int e = blockIdx.x * blockDim.x + threadIdx.x;
    if (e >= DDW) return;
    int n = e >> 9, k = e & 511;
    d[e] = __float2half_rn(src[n * 1536 + k * 3]);
}

__global__ void transpose_w9(const float* __restrict__ w1, const float* __restrict__ w2,
                             const float* __restrict__ w3, __half* __restrict__ dst)
{
    __shared__ float tile[32][33];
    int z = blockIdx.z;
    int stage = z / 3, which = z - stage * 3;
    const float* src = (stage == 0 ? w1 : (stage == 1 ? w2 : w3)) + (size_t)which * DDW;
    __half* d = dst + (size_t)z * DDW;
    int bx = blockIdx.x << 5, by = blockIdx.y << 5;
    int tx = threadIdx.x, ty = threadIdx.y;   // (32, 8)
    #pragma unroll
    for (int j = 0; j < 32; j += 8)
        tile[ty + j][tx] = src[(size_t)(by + ty + j) * 512 + bx + tx];
    __syncthreads();
    #pragma unroll
    for (int j = 0; j < 32; j += 8)
        d[(size_t)(bx + ty + j) * 512 + by + tx] = __float2half_rn(tile[tx][ty + j]);
}

__global__ void mkbias3(const float* __restrict__ w1, const float* __restrict__ w2,
                        const float* __restrict__ w3,
                        const float* __restrict__ b1, const float* __restrict__ b2,
                        const float* __restrict__ b3,
                        float* __restrict__ b1024)
{
    int s = blockIdx.y;
    const float* Wsel = (s == 0 ? w1 : (s == 1 ? w2 : w3));
    const float* bsel = (s == 0 ? b1 : (s == 1 ? b2 : b3));
    const float* Wo = Wsel + 3*DDW;
    const float* bv = bsel + 2*ND;
    const float* bo = bsel + 3*ND;
    float* bout = b1024 + s * 1024;
    int tid = threadIdx.x, wid = tid >> 5, lane = tid & 31;

    if (tid < 32) bout[blockIdx.x * 32 + tid] = 0.f;

    #pragma unroll
    for (int i = 0; i < 4; i++){
        int n = blockIdx.x * 32 + wid * 4 + i;
        const float* row = Wo + (size_t)n * 512;
        float sum = 0.f;
        #pragma unroll
        for (int j = 0; j < 16; j++)
            sum += row[lane + j * 32] * bv[lane + j * 32];
        #pragma unroll
        for (int off = 16; off > 0; off >>= 1)
            sum += __shfl_down_sync(0xffffffff, sum, off);
        if (lane == 0) bout[512 + n] = sum + bo[n];
    }
}

// topk + softmax; zeroes g_mean after use (saves per-stage memsets)
__global__ void topk_kernel()
{
    __shared__ float gv[NL];
    __shared__ float rv[512];
    __shared__ int   ri[512];
    __shared__ int   sidx[NTOPK];
    int tid = threadIdx.x;
    for (int t = tid; t < NL; t += 512) {
        float s = 0.f;
        for (int b = 0; b < NB; b++) s += g_mean[b * NL + t];
        gv[t] = s;
    }
    __syncthreads();
    for (int it = 0; it < NTOPK; it++) {
        float bv = -INFINITY; int bi = 0x7fffffff;
        for (int t = tid; t < NL; t += 512) {
            float v = gv[t];
            if (v > bv || (v == bv && t < bi)) { bv = v; bi = t; }
        }
        rv[tid] = bv; ri[tid] = bi;
        __syncthreads();
        for (int s = 256; s > 0; s >>= 1) {
            if (tid < s) {
                if (rv[tid+s] > rv[tid] || (rv[tid+s] == rv[tid] && ri[tid+s] < ri[tid])) {
                    rv[tid] = rv[tid+s]; ri[tid] = ri[tid+s];
                }
            }
            __syncthreads();
        }
        if (tid == 0) { sidx[it] = ri[0]; gv[ri[0]] = -INFINITY; }
        __syncthreads();
    }
    if (tid < NTOPK) g_idx[tid] = sidx[tid];
    if (tid < NB) {
        float vals[NTOPK];
        float mx = -INFINITY;
        for (int i = 0; i < NTOPK; i++) {
            vals[i] = g_mean[tid * NL + sidx[i]];
            mx = fmaxf(mx, vals[i]);
        }
        float s = 0.f;
        for (int i = 0; i < NTOPK; i++) { vals[i] = expf(vals[i] - mx); s += vals[i]; }
        float inv = 1.f / s;
        for (int i = 0; i < NTOPK; i++) g_wt[tid * NTOPK + i] = vals[i] * inv;
    }
    __syncthreads();
    for (int t = tid; t < NB * NL; t += 512) g_mean[t] = 0.f;
}

__global__ void roll_kernel(const __half* __restrict__ V16, const float* __restrict__ R,
                            float* __restrict__ Of, __half* __restrict__ O16)
{
    int e = blockIdx.x * blockDim.x + threadIdx.x;
    if (e >= NBLD/2) return;
    int dh = e & 255;
    int row = e >> 8;
    int b = row / NL;
    int t = row - b * NL;
    float2 r2 = *reinterpret_cast<const float2*>(R + (size_t)row * ND + dh*2);
    float sx = r2.x, sy = r2.y;
    #pragma unroll
    for (int i = 0; i < NTOPK; i++) {
        int tt = t + g_idx[i];
        if (tt >= NL) tt -= NL;
        __half2 v = *reinterpret_cast<const __half2*>(V16 + ((size_t)(b*NL + tt))*ND + dh*2);
        float2 vf = __half22float2(v);
        float w = g_wt[b * NTOPK + i];
        sx += w * vf.x; sy += w * vf.y;
    }
    *reinterpret_cast<float2*>(Of + (size_t)row * ND + dh*2) = make_float2(sx, sy);
    if (O16)
        *reinterpret_cast<__half2*>(O16 + (size_t)row * ND + dh*2) = __floats2half2_rn(sx, sy);
}

__global__ void decomp_kernel(const float* __restrict__ X, float* __restrict__ Of,
                              __half* O16)
{
    int i = blockIdx.x * blockDim.x + threadIdx.x;
    if (i >= NBLD/8) return;
    int d = i & 511;
    int c = i >> 9;
    int b = c / (NL/8);
    int tb = (c - b * (NL/8)) * 8;
    const float* Xb = X + (size_t)b * NL * ND + d;

    float acc = 0.f;
    #pragma unroll
    for (int u = -12; u <= 12; u++){
        int t = tb + u;
        t = t < 0 ? 0 : (t >= NL ? NL - 1 : t);
        acc += Xb[(size_t)t * ND];
    }
    #pragma unroll
    for (int j = 0; j < 8; j++){
        int t = tb + j;
        float x = Xb[(size_t)t * ND];
        float v = x - acc * (1.f / 25.f);
        size_t e = ((size_t)b * NL + t) * ND + d;
        if (Of)  Of[e]  = v;
        if (O16) O16[e] = __float2half_rn(v);
        int ta = t + 13; ta = ta >= NL ? NL - 1 : ta;
        int ts = t - 12; ts = ts < 0 ? 0 : ts;
        acc += Xb[(size_t)ta * ND] - Xb[(size_t)ts * ND];
    }
}

// ------------------------------- host side -----------------------------------
#define GETSYM(var, sym) do{ cudaGetSymbolAddress((void**)&var, sym); }while(0)

extern "C" void kernel_launch(void* const* d_in, const int* in_sizes, int n_in,
                              void* d_out, int out_size)
{
    const float* x_s      = (const float*)d_in[0];
    const float* x_w      = (const float*)d_in[1];
    const float* wc1_W    = (const float*)d_in[2];
    const float* wc1_b    = (const float*)d_in[3];
    const float* wc2_W    = (const float*)d_in[4];
    const float* wc2_b    = (const float*)d_in[5];
    const float* attn_W   = (const float*)d_in[6];
    const float* attn_b   = (const float*)d_in[7];
    const float* wc1_proj = (const float*)d_in[8];
    const float* wc2_proj = (const float*)d_in[9];
    const float* conv1_W  = (const float*)d_in[10];
    const float* conv2_W  = (const float*)d_in[11];
    float* out  = (float*)d_out;
    float* out2 = out + NBLD;

    float *pxs, *pxs2, *ptmp, *pv32, *pmean, *pb1024;
    GETSYM(pxs, g_xs); GETSYM(pxs2, g_xs2); GETSYM(ptmp, g_tmp);
    GETSYM(pv32, g_v32); GETSYM(pmean, g_mean); GETSYM(pb1024, g_b1024);
    __half *wf, *pweh, *pwmv, *pwtt;
    GETSYM(wf, g_wf); GETSYM(pweh, g_weh); GETSYM(pwmv, g_wmv); GETSYM(pwtt, g_wtt);
    __half *pfXW,*pfXSI,*pfK,*pfV,*pfXSa,*pfXS2,*pfXW1,*pfXSB,*pfH;
    GETSYM(pfXW, fXW);   GETSYM(pfXSI, fXSI);
    GETSYM(pfK, fK);     GETSYM(pfV, fV);
    GETSYM(pfXSa, fXSa); GETSYM(pfXS2, fXS2);
    GETSYM(pfXW1, fXW1); GETSYM(pfXSB, fXSB); GETSYM(pfH, fH);

    cudaFuncSetAttribute(gemm_s,    cudaFuncAttributeMaxDynamicSharedMemorySize, 2*SSTG);
    cudaFuncSetAttribute(gemm_w,    cudaFuncAttributeMaxDynamicSharedMemorySize, 2*SSTG);
    cudaFuncSetAttribute(embed_f16, cudaFuncAttributeMaxDynamicSharedMemorySize, 2*SSTG);
    cudaFuncSetAttribute(corr_f16,  cudaFuncAttributeMaxDynamicSharedMemorySize, 2*SSTG);

    static cudaStream_t s2 = nullptr, s3 = nullptr;
    static cudaEvent_t evCvt=nullptr, evB=nullptr, evF=nullptr, evW=nullptr,
                       evVA=nullptr, evVC=nullptr, evVE=nullptr,
                       evRollA=nullptr, evD=nullptr;
    if (s2 == nullptr){
        cudaStreamCreateWithFlags(&s2, cudaStreamNonBlocking);
        cudaStreamCreateWithFlags(&s3, cudaStreamNonBlocking);
        cudaEventCreateWithFlags(&evCvt,  cudaEventDisableTiming);
        cudaEventCreateWithFlags(&evB,    cudaEventDisableTiming);
        cudaEventCreateWithFlags(&evF,    cudaEventDisableTiming);
        cudaEventCreateWithFlags(&evW,    cudaEventDisableTiming);
        cudaEventCreateWithFlags(&evVA,   cudaEventDisableTiming);
        cudaEventCreateWithFlags(&evVC,   cudaEventDisableTiming);
        cudaEventCreateWithFlags(&evVE,   cudaEventDisableTiming);
        cudaEventCreateWithFlags(&evRollA,cudaEventDisableTiming);
        cudaEventCreateWithFlags(&evD,    cudaEventDisableTiming);
    }

    const int nRB = (NBLD/2 + 255) / 256;
    const int nDB = (NBLD/8 + 255) / 256;
    dim3 corrG(12, 12, NB);
    dim3 embG(4, 192);

    auto G = [&](const __half* A, const __half* W, const float* bias, const float* R,
                 float* Cf, __half* C16, int N, int K, int relu, cudaStream_t st){
        dim3 g(N >> 7, MTOT >> 7);
        gemm_s<<<g, 256, 2*SSTG, st>>>(A, W, bias, R, Cf, C16, N, K, relu);
    };

    // ---- weight + input conversions (batched, stream 0) ---------------------
    {
        dim3 cg(1024, 1, 5);
        cvt_f16s_b<<<cg, 256>>>(wc1_W, attn_W, wc2_W, conv1_W, conv2_W,
                                wf, wf + 4*(size_t)DDW, wf + 8*(size_t)DDW,
                                wf + 12*(size_t)DDW, wf + 16*(size_t)DDW, DDW);
        dim3 pg((DDW+255)/256, 1, 6);
        cvt_proj_f16<<<pg, 256>>>(wc1_proj, wc2_proj, pweh);
        dim3 ig((NBLD/4+255)/256, 1, 2);
        cvt_f16s_b<<<ig, 256>>>(x_w, x_s, nullptr, nullptr, nullptr,
                                pfXW, pfXSI, nullptr, nullptr, nullptr, NBLD/4);
    }

    // ---- fork: embed chain on s2 --------------------------------------------
    cudaEventRecord(evCvt, 0);
    cudaStreamWaitEvent(s2, evCvt, 0);
    embed_f16<<<embG, 256, 2*SSTG, s2>>>(pfXW, pweh, nullptr, pfXW1);
    cudaEventRecord(evB, s2);
    embed_f16<<<embG, 256, 2*SSTG, s2>>>(pfXW1, pweh + 3*(size_t)DDW, out2, nullptr);
    cudaEventRecord(evF, s2);

    // ---- folded weight products (batched prologue, stream 0) ----------------
    {
        dim3 trG(16, 16, 9), trB(32, 8);
        transpose_w9<<<trG, trB>>>(wc1_W, attn_W, wc2_W, pwtt);
        dim3 wg(4, 4, 6);
        gemm_w<<<wg, 256, 2*SSTG>>>(pwtt, wf, pwmv);
        dim3 mbG(16, 3);
        mkbias3<<<mbG, 256>>>(wc1_W, attn_W, wc2_W, wc1_b, attn_b, wc2_b, pb1024);
        cudaMemsetAsync(pmean, 0, NB*NL*sizeof(float), 0);
    }
    cudaEventRecord(evW, 0);

    // ---- v' GEMMs on s3 (one per stage, gated on dependencies) --------------
    // stage A v': needs weights (evW) + pfXSI (cvt, before evW on stream 0)
    cudaStreamWaitEvent(s3, evW, 0);
    G(pfXSI, pwmv + 1*(size_t)DDW, pb1024 + 512, nullptr, nullptr, pfV, ND, ND, 0, s3);
    cudaEventRecord(evVA, s3);

    // ---- stage A: k~ -> corr -> topk ; roll joins v' ------------------------
    G(pfXSI, pwmv + 0*(size_t)DDW, nullptr, nullptr, nullptr, pfK, ND, ND, 0, 0);
    corr_f16<<<corrG, 256, 2*SSTG>>>(pfXW, pfK);
    topk_kernel<<<1, 512>>>();
    cudaStreamWaitEvent(0, evVA, 0);
    roll_kernel<<<nRB, 256>>>(pfV, x_s, pxs, pfXSa);
    cudaEventRecord(evRollA, 0);

    // stage C v' on s3: needs pfXSa (roll A) — also covers pfV WAR vs roll A
    cudaStreamWaitEvent(s3, evRollA, 0);
    G(pfXSa, pwmv + 3*(size_t)DDW, pb1024 + 1024 + 512, nullptr, nullptr, pfV, ND, ND, 0, s3);
    cudaEventRecord(evVC, s3);

    // ---- stage C ------------------------------------------------------------
    G(pfXSa, pwmv + 2*(size_t)DDW, nullptr, nullptr, nullptr, pfK, ND, ND, 0, 0);
    corr_f16<<<corrG, 256, 2*SSTG>>>(pfXSa, pfK);
    topk_kernel<<<1, 512>>>();
    cudaStreamWaitEvent(0, evVC, 0);
    roll_kernel<<<nRB, 256>>>(pfV, pxs, pxs, nullptr);

    // ---- stage D: xs2 = series_decomp(xs) -----------------------------------
    decomp_kernel<<<nDB, 256>>>(pxs, pxs2, pfXS2);
    cudaEventRecord(evD, 0);

    // stage E v' on s3: needs pfXS2 (decomp D) — also covers pfV WAR vs roll C
    cudaStreamWaitEvent(s3, evD, 0);
    G(pfXS2, pwmv + 5*(size_t)DDW, pb1024 + 2048 + 512, nullptr, nullptr, pfV, ND, ND, 0, s3);
    cudaEventRecord(evVE, s3);

    // ---- stage E ------------------------------------------------------------
    G(pfXS2, pwmv + 4*(size_t)DDW, nullptr, nullptr, nullptr, pfK, ND, ND, 0, 0);
    cudaStreamWaitEvent(0, evB, 0);      // corr E reads pfXW1 (embed B on s2)
    corr_f16<<<corrG, 256, 2*SSTG>>>(pfXW1, pfK);
    topk_kernel<<<1, 512>>>();
    cudaStreamWaitEvent(0, evVE, 0);
    roll_kernel<<<nRB, 256>>>(pfV, pxs2, ptmp, pfXSB);

    // ---- stage G: FFN + final series_decomp -> out --------------------------
    G(pfXSB, wf + 12*(size_t)DDW, nullptr, nullptr, nullptr, pfH, NDFF, ND,   1, 0);
    G(pfH,   wf + 16*(size_t)DDW, nullptr, ptmp,    pv32,    nullptr, ND, NDFF, 0, 0);
    decomp_kernel<<<nDB, 256>>>(pv32, out, nullptr);

    // ---- join: out2 (stage F on s2) must complete before graph end ----------
    cudaStreamWaitEvent(0, evF, 0);
}